// round 2
// baseline (speedup 1.0000x reference)
#include <cuda_runtime.h>
#include <cuda_bf16.h>

#define NN   50000
#define EE   800000
#define ET   (EE + NN)      // edges + self loops = 850000
#define DIN  128
#define HIDN 64
#define OUTC 32
#define NB   64             // number of graphs
#define NHEAD 4
#define C1   16             // HID/HEADS

#define NEG_SLOPE 0.2f
#define BN_EPS 1e-5f

// ---------------- scratch (device globals; no allocation allowed) ------------
__device__ float d_xl1[NN * HIDN];
__device__ float d_es1[NN * NHEAD];
__device__ float d_ed1[NN * NHEAD];
__device__ float d_e1[ET * NHEAD];
__device__ float d_m1[NN * NHEAD];
__device__ float d_s1[NN * NHEAD];
__device__ float d_h1[NN * HIDN];
__device__ float d_stats1[2 * HIDN];

__device__ float d_xl2[NN * OUTC];
__device__ float d_es2[NN];
__device__ float d_ed2[NN];
__device__ float d_e2[ET];
__device__ float d_m2[NN];
__device__ float d_s2[NN];
__device__ float d_h2[NN * OUTC];
__device__ float d_stats2[2 * OUTC];

__device__ float d_gsum[NB * OUTC];
__device__ float d_gmax[NB * OUTC];
__device__ float d_gcnt[NB];

__device__ __forceinline__ float NEG_INF() { return __int_as_float(0xff800000); }

__device__ __forceinline__ void atomicMaxF(float* addr, float v) {
    if (v >= 0.0f) atomicMax((int*)addr, __float_as_int(v));
    else           atomicMin((unsigned int*)addr, __float_as_uint(v));
}

// ---------------- GEMM1: xl1 = x @ W1  ([N,128]@[128,64]) --------------------
__global__ __launch_bounds__(256) void k_gemm1(const float* __restrict__ x,
                                               const float* __restrict__ W1) {
    __shared__ float Ws[DIN * HIDN];   // 32 KB
    __shared__ float xs[4][DIN];
    int tid = threadIdx.x;             // 256
    for (int i = tid; i < DIN * HIDN; i += 256) Ws[i] = W1[i];
    int col = tid & 63;
    int r   = tid >> 6;
    for (int row0 = blockIdx.x * 4; row0 < NN; row0 += gridDim.x * 4) {
        __syncthreads();
        for (int i = tid; i < 4 * DIN; i += 256) {
            int rr = i >> 7, k = i & 127;
            int row = row0 + rr;
            xs[rr][k] = (row < NN) ? x[row * DIN + k] : 0.f;
        }
        __syncthreads();
        int row = row0 + r;
        if (row < NN) {
            float acc = 0.f;
            #pragma unroll
            for (int k = 0; k < DIN; k++) acc = fmaf(xs[r][k], Ws[k * HIDN + col], acc);
            d_xl1[row * HIDN + col] = acc;
        }
    }
}

// ---------------- prep1: per-node attention logits, init scratch -------------
__global__ __launch_bounds__(256) void k_prep1(const float* __restrict__ a_src,
                                               const float* __restrict__ a_dst) {
    int gt = blockIdx.x * blockDim.x + threadIdx.x;
    if (gt < 2 * HIDN) d_stats1[gt] = 0.f;
    if (gt >= NN * NHEAD) return;
    int n = gt >> 2, h = gt & 3;
    const float4* xr = (const float4*)(d_xl1 + n * HIDN + h * C1);
    const float4* as = (const float4*)(a_src + h * C1);
    const float4* ad = (const float4*)(a_dst + h * C1);
    float s = 0.f, d = 0.f;
    float4* hz = (float4*)(d_h1 + n * HIDN + h * C1);
    #pragma unroll
    for (int i = 0; i < 4; i++) {
        float4 v = xr[i], a = as[i], b = ad[i];
        s += v.x * a.x + v.y * a.y + v.z * a.z + v.w * a.w;
        d += v.x * b.x + v.y * b.y + v.z * b.z + v.w * b.w;
        hz[i] = make_float4(0.f, 0.f, 0.f, 0.f);
    }
    d_es1[gt] = s;
    d_ed1[gt] = d;
    d_m1[gt] = NEG_INF();
    d_s1[gt] = 0.f;
}

// ---------------- layer-1 edge passes ----------------------------------------
__global__ __launch_bounds__(256) void k_edge_max1(const int* __restrict__ ei) {
    int idx = blockIdx.x * blockDim.x + threadIdx.x;
    if (idx >= ET * NHEAD) return;
    int i = idx >> 2, h = idx & 3;
    int src, dst;
    if (i < EE) { src = ei[i]; dst = ei[EE + i]; } else { src = dst = i - EE; }
    float e = d_es1[src * 4 + h] + d_ed1[dst * 4 + h];
    e = e > 0.f ? e : NEG_SLOPE * e;
    d_e1[idx] = e;
    atomicMaxF(&d_m1[dst * 4 + h], e);
}

__global__ __launch_bounds__(256) void k_edge_sum1(const int* __restrict__ ei) {
    int idx = blockIdx.x * blockDim.x + threadIdx.x;
    if (idx >= ET * NHEAD) return;
    int i = idx >> 2, h = idx & 3;
    int dst;
    if (i < EE) { dst = ei[EE + i]; } else { dst = i - EE; }
    float p = expf(d_e1[idx] - d_m1[dst * 4 + h]);
    d_e1[idx] = p;
    atomicAdd(&d_s1[dst * 4 + h], p);
}

__global__ __launch_bounds__(256) void k_edge_agg1(const int* __restrict__ ei) {
    int idx = blockIdx.x * blockDim.x + threadIdx.x;
    if (idx >= ET * HIDN) return;
    int i = idx >> 6, col = idx & 63, h = col >> 4;
    int src, dst;
    if (i < EE) { src = ei[i]; dst = ei[EE + i]; } else { src = dst = i - EE; }
    float alpha = d_e1[i * 4 + h] / (d_s1[dst * 4 + h] + 1e-16f);
    atomicAdd(&d_h1[dst * HIDN + col], alpha * d_xl1[src * HIDN + col]);
}

// ---------------- batch-norm (generic stats over columns) --------------------
__global__ __launch_bounds__(256) void k_bn_stats(const float* __restrict__ data,
                                                  float* __restrict__ stats,
                                                  int ncols, int total) {
    int tid = blockIdx.x * blockDim.x + threadIdx.x;
    int nth = gridDim.x * blockDim.x;    // multiple of ncols
    float s = 0.f, ss = 0.f;
    for (int i = tid; i < total; i += nth) {
        float v = data[i];
        s += v; ss += v * v;
    }
    int col = tid % ncols;
    atomicAdd(&stats[col], s);
    atomicAdd(&stats[ncols + col], ss);
}

__global__ __launch_bounds__(256) void k_bn_apply1(const float* __restrict__ g1,
                                                   const float* __restrict__ be1) {
    int i = blockIdx.x * blockDim.x + threadIdx.x;
    if (i >= NN * HIDN) return;
    int col = i & 63;
    float mu  = d_stats1[col] * (1.0f / NN);
    float var = d_stats1[HIDN + col] * (1.0f / NN) - mu * mu;
    float v = (d_h1[i] - mu) * rsqrtf(var + BN_EPS) * g1[col] + be1[col];
    d_h1[i] = fmaxf(v, 0.f);
}

// ---------------- GEMM2: xl2 = h1 @ W2  ([N,64]@[64,32]) ---------------------
__global__ __launch_bounds__(256) void k_gemm2(const float* __restrict__ W2) {
    __shared__ float Ws[HIDN * OUTC];   // 8 KB
    __shared__ float xs[8][HIDN];
    int tid = threadIdx.x;              // 256
    for (int i = tid; i < HIDN * OUTC; i += 256) Ws[i] = W2[i];
    int col = tid & 31;
    int r   = tid >> 5;
    for (int row0 = blockIdx.x * 8; row0 < NN; row0 += gridDim.x * 8) {
        __syncthreads();
        for (int i = tid; i < 8 * HIDN; i += 256) {
            int rr = i >> 6, k = i & 63;
            int row = row0 + rr;
            xs[rr][k] = (row < NN) ? d_h1[row * HIDN + k] : 0.f;
        }
        __syncthreads();
        int row = row0 + r;
        if (row < NN) {
            float acc = 0.f;
            #pragma unroll
            for (int k = 0; k < HIDN; k++) acc = fmaf(xs[r][k], Ws[k * OUTC + col], acc);
            d_xl2[row * OUTC + col] = acc;
        }
    }
}

// ---------------- prep2: warp per node; also zero pooling buffers ------------
__global__ __launch_bounds__(256) void k_prep2(const float* __restrict__ a_src,
                                               const float* __restrict__ a_dst) {
    int gt = blockIdx.x * blockDim.x + threadIdx.x;
    if (gt < NB * OUTC) { d_gsum[gt] = 0.f; d_gmax[gt] = NEG_INF(); }
    if (gt < NB) d_gcnt[gt] = 0.f;
    if (gt < 2 * OUTC) d_stats2[gt] = 0.f;
    if (gt >= NN * 32) return;
    int n = gt >> 5, lane = gt & 31;
    float v = d_xl2[n * OUTC + lane];
    float s = v * a_src[lane];
    float d = v * a_dst[lane];
    #pragma unroll
    for (int o = 16; o > 0; o >>= 1) {
        s += __shfl_down_sync(0xffffffffu, s, o);
        d += __shfl_down_sync(0xffffffffu, d, o);
    }
    if (lane == 0) {
        d_es2[n] = s; d_ed2[n] = d;
        d_m2[n] = NEG_INF(); d_s2[n] = 0.f;
    }
    d_h2[n * OUTC + lane] = 0.f;
}

// ---------------- layer-2 edge passes (H=1) ----------------------------------
__global__ __launch_bounds__(256) void k_edge_max2(const int* __restrict__ ei) {
    int i = blockIdx.x * blockDim.x + threadIdx.x;
    if (i >= ET) return;
    int src, dst;
    if (i < EE) { src = ei[i]; dst = ei[EE + i]; } else { src = dst = i - EE; }
    float e = d_es2[src] + d_ed2[dst];
    e = e > 0.f ? e : NEG_SLOPE * e;
    d_e2[i] = e;
    atomicMaxF(&d_m2[dst], e);
}

__global__ __launch_bounds__(256) void k_edge_sum2(const int* __restrict__ ei) {
    int i = blockIdx.x * blockDim.x + threadIdx.x;
    if (i >= ET) return;
    int dst;
    if (i < EE) { dst = ei[EE + i]; } else { dst = i - EE; }
    float p = expf(d_e2[i] - d_m2[dst]);
    d_e2[i] = p;
    atomicAdd(&d_s2[dst], p);
}

__global__ __launch_bounds__(256) void k_edge_agg2(const int* __restrict__ ei) {
    int idx = blockIdx.x * blockDim.x + threadIdx.x;
    if (idx >= ET * OUTC) return;
    int i = idx >> 5, col = idx & 31;
    int src, dst;
    if (i < EE) { src = ei[i]; dst = ei[EE + i]; } else { src = dst = i - EE; }
    float alpha = d_e2[i] / (d_s2[dst] + 1e-16f);
    atomicAdd(&d_h2[dst * OUTC + col], alpha * d_xl2[src * OUTC + col]);
}

// ---------------- BN2 + write node_emb + pooling -----------------------------
__global__ __launch_bounds__(256) void k_bn2_pool(const float* __restrict__ g2,
                                                  const float* __restrict__ be2,
                                                  const int* __restrict__ batch,
                                                  float* __restrict__ out) {
    int i = blockIdx.x * blockDim.x + threadIdx.x;
    if (i >= NN * OUTC) return;
    int col = i & 31, n = i >> 5;
    float mu  = d_stats2[col] * (1.0f / NN);
    float var = d_stats2[OUTC + col] * (1.0f / NN) - mu * mu;
    float v = (d_h2[i] - mu) * rsqrtf(var + BN_EPS) * g2[col] + be2[col];
    out[i] = v;
    int b = batch[n];
    atomicAdd(&d_gsum[b * OUTC + col], v);
    atomicMaxF(&d_gmax[b * OUTC + col], v);
    if (col == 0) atomicAdd(&d_gcnt[b], 1.f);
}

// ---------------- final MLP over graph embeddings ----------------------------
__global__ __launch_bounds__(256) void k_final(const float* __restrict__ fcW1,
                                               const float* __restrict__ fcb1,
                                               const float* __restrict__ fcW2,
                                               const float* __restrict__ fcb2,
                                               float* __restrict__ out) {
    __shared__ float g[NB * 2 * OUTC];   // [64][64]
    __shared__ float t[NB * OUTC];       // [64][32]
    int tid = threadIdx.x;               // 256
    for (int i = tid; i < NB * 2 * OUTC; i += 256) {
        int b = i >> 6, j = i & 63;
        float v;
        if (j < OUTC) {
            v = d_gsum[b * OUTC + j] / fmaxf(d_gcnt[b], 1.f);
        } else {
            v = d_gmax[b * OUTC + (j - OUTC)];
            if (v < -3e37f) v = 0.f;    // isfinite guard for empty graphs
        }
        g[i] = v;
    }
    __syncthreads();
    for (int i = tid; i < NB * OUTC; i += 256) {
        int b = i >> 5, o = i & 31;
        float acc = fcb1[o];
        #pragma unroll
        for (int j = 0; j < 2 * OUTC; j++) acc = fmaf(g[b * 64 + j], fcW1[j * OUTC + o], acc);
        t[i] = fmaxf(acc, 0.f);
    }
    __syncthreads();
    for (int i = tid; i < NB * OUTC; i += 256) {
        int b = i >> 5, o = i & 31;
        float acc = fcb2[o];
        #pragma unroll
        for (int j = 0; j < OUTC; j++) acc = fmaf(t[b * OUTC + j], fcW2[j * OUTC + o], acc);
        out[NN * OUTC + i] = acc;
    }
}

// =============================================================================
extern "C" void kernel_launch(void* const* d_in, const int* in_sizes, int n_in,
                              void* d_out, int out_size) {
    const float* x      = (const float*)d_in[0];
    const int*   ei     = (const int*)  d_in[1];
    const int*   batch  = (const int*)  d_in[2];
    const float* W1     = (const float*)d_in[3];
    const float* a_src1 = (const float*)d_in[4];
    const float* a_dst1 = (const float*)d_in[5];
    // d_in[6] = b1 (cancels in BN)
    const float* g1     = (const float*)d_in[7];
    const float* be1    = (const float*)d_in[8];
    const float* W2     = (const float*)d_in[9];
    const float* a_src2 = (const float*)d_in[10];
    const float* a_dst2 = (const float*)d_in[11];
    // d_in[12] = b2 (cancels in BN)
    const float* g2     = (const float*)d_in[13];
    const float* be2    = (const float*)d_in[14];
    const float* fcW1   = (const float*)d_in[15];
    const float* fcb1   = (const float*)d_in[16];
    const float* fcW2   = (const float*)d_in[17];
    const float* fcb2   = (const float*)d_in[18];
    float* out = (float*)d_out;

    float* p_h1;  cudaGetSymbolAddress((void**)&p_h1,  d_h1);
    float* p_st1; cudaGetSymbolAddress((void**)&p_st1, d_stats1);
    float* p_h2;  cudaGetSymbolAddress((void**)&p_h2,  d_h2);
    float* p_st2; cudaGetSymbolAddress((void**)&p_st2, d_stats2);

    // layer 1
    k_gemm1<<<592, 256>>>(x, W1);
    k_prep1<<<(NN * NHEAD + 255) / 256, 256>>>(a_src1, a_dst1);
    k_edge_max1<<<(ET * NHEAD + 255) / 256, 256>>>(ei);
    k_edge_sum1<<<(ET * NHEAD + 255) / 256, 256>>>(ei);
    k_edge_agg1<<<(ET * HIDN + 255) / 256, 256>>>(ei);
    k_bn_stats<<<64, 256>>>(p_h1, p_st1, HIDN, NN * HIDN);
    k_bn_apply1<<<(NN * HIDN + 255) / 256, 256>>>(g1, be1);

    // layer 2
    k_gemm2<<<592, 256>>>(W2);
    k_prep2<<<(NN * 32 + 255) / 256, 256>>>(a_src2, a_dst2);
    k_edge_max2<<<(ET + 255) / 256, 256>>>(ei);
    k_edge_sum2<<<(ET + 255) / 256, 256>>>(ei);
    k_edge_agg2<<<(ET * OUTC + 255) / 256, 256>>>(ei);
    k_bn_stats<<<64, 256>>>(p_h2, p_st2, OUTC, NN * OUTC);
    k_bn2_pool<<<(NN * OUTC + 255) / 256, 256>>>(g2, be2, batch, out);

    // graph head
    k_final<<<1, 256>>>(fcW1, fcb1, fcW2, fcb2, out);
}

// round 3
// speedup vs baseline: 1.5580x; 1.5580x over previous
#include <cuda_runtime.h>
#include <cuda_bf16.h>

#define NN   50000
#define EE   800000
#define ET   (EE + NN)      // edges + self loops = 850000
#define DIN  128
#define HIDN 64
#define OUTC 32
#define NB   64             // number of graphs
#define NHEAD 4
#define C1   16             // HID/HEADS

#define NEG_SLOPE 0.2f
#define BN_EPS 1e-5f

// ---------------- scratch (device globals; no allocation allowed) ------------
__device__ float d_xl1[NN * HIDN];
__device__ float d_es1[NN * NHEAD];
__device__ float d_ed1[NN * NHEAD];
__device__ float d_h1[NN * HIDN];
__device__ float d_stats1[2 * HIDN];

__device__ float d_xl2[NN * OUTC];
__device__ float d_es2[NN];
__device__ float d_ed2[NN];
__device__ float d_h2[NN * OUTC];
__device__ float d_stats2[2 * OUTC];

__device__ float d_gsum[NB * OUTC];
__device__ float d_gmax[NB * OUTC];
__device__ float d_gcnt[NB];

// CSR (by dst)
__device__ int d_deg[NN];
__device__ int d_off[NN + 1];
__device__ int d_cursor[NN];
__device__ int d_csrc[ET];

__device__ __forceinline__ float NEG_INF() { return __int_as_float(0xff800000); }

__device__ __forceinline__ void atomicMaxF(float* addr, float v) {
    if (v >= 0.0f) atomicMax((int*)addr, __float_as_int(v));
    else           atomicMin((unsigned int*)addr, __float_as_uint(v));
}

__device__ __forceinline__ float lrelu(float e) { return e > 0.f ? e : NEG_SLOPE * e; }

// packed f32x2 helpers (sm_100+)
__device__ __forceinline__ unsigned long long pack2dup(float x) {
    unsigned long long r;
    asm("mov.b64 %0, {%1,%2};" : "=l"(r) : "f"(x), "f"(x));
    return r;
}
__device__ __forceinline__ unsigned long long ffma2(unsigned long long a,
                                                    unsigned long long b,
                                                    unsigned long long c) {
    unsigned long long d;
    asm("fma.rn.f32x2 %0, %1, %2, %3;" : "=l"(d) : "l"(a), "l"(b), "l"(c));
    return d;
}
__device__ __forceinline__ float2 unpack2(unsigned long long v) {
    float2 f;
    asm("mov.b64 {%0,%1}, %2;" : "=f"(f.x), "=f"(f.y) : "l"(v));
    return f;
}

// ---------------- CSR build ---------------------------------------------------
__global__ __launch_bounds__(256) void k_deg_init() {
    int i = blockIdx.x * blockDim.x + threadIdx.x;
    if (i >= NN) return;
    d_deg[i] = 1;                       // self loop
    if (i < 2 * HIDN) d_stats1[i] = 0.f;
    if (i < 2 * OUTC) d_stats2[i] = 0.f;
    if (i < NB * OUTC) { d_gsum[i] = 0.f; d_gmax[i] = NEG_INF(); }
    if (i < NB) d_gcnt[i] = 0.f;
}

__global__ __launch_bounds__(256) void k_deg_count(const int* __restrict__ ei) {
    int i = blockIdx.x * blockDim.x + threadIdx.x;
    if (i >= EE) return;
    atomicAdd(&d_deg[ei[EE + i]], 1);
}

__global__ __launch_bounds__(1024) void k_scan() {
    __shared__ int part[1024];
    const int CH = (NN + 1023) / 1024;   // 49
    int t = threadIdx.x;
    int base = t * CH;
    int lim = min(base + CH, NN);
    int s = 0;
    for (int i = base; i < lim; i++) s += d_deg[i];
    part[t] = s;
    __syncthreads();
    for (int off = 1; off < 1024; off <<= 1) {
        int v = (t >= off) ? part[t - off] : 0;
        __syncthreads();
        part[t] += v;
        __syncthreads();
    }
    int run = (t == 0) ? 0 : part[t - 1];
    for (int i = base; i < lim; i++) {
        d_off[i] = run;
        d_cursor[i] = run;
        run += d_deg[i];
    }
    if (t == 0) d_off[NN] = part[1023];
}

__global__ __launch_bounds__(256) void k_fill(const int* __restrict__ ei) {
    int i = blockIdx.x * blockDim.x + threadIdx.x;
    if (i >= ET) return;
    int src, dst;
    if (i < EE) { src = ei[i]; dst = ei[EE + i]; } else { src = dst = i - EE; }
    int pos = atomicAdd(&d_cursor[dst], 1);
    d_csrc[pos] = src;
}

// ---------------- GEMM1: xl1 = x @ W1  ([N,128]@[128,64]) via f32x2 ----------
__global__ __launch_bounds__(256) void k_gemm1(const float* __restrict__ x,
                                               const float* __restrict__ W1) {
    __shared__ float2 Ws2[DIN * 32];    // [k][colpair]  32 KB
    __shared__ float  xs[32][DIN];      // 16 KB
    int tid = threadIdx.x;
    for (int i = tid; i < DIN * 32; i += 256) {
        int k = i >> 5, cp = i & 31;
        Ws2[i] = *(const float2*)&W1[k * HIDN + (cp << 1)];
    }
    const unsigned long long* Wsu = (const unsigned long long*)Ws2;
    int cp = tid & 31;
    int w  = tid >> 5;                  // warp id -> row quad
    for (int row0 = blockIdx.x * 32; row0 < NN; row0 += gridDim.x * 32) {
        __syncthreads();
        for (int i = tid; i < 32 * DIN; i += 256) {
            int rr = i >> 7, k = i & 127;
            int row = row0 + rr;
            xs[rr][k] = (row < NN) ? x[row * DIN + k] : 0.f;
        }
        __syncthreads();
        unsigned long long a0 = 0ull, a1 = 0ull, a2 = 0ull, a3 = 0ull;
        int r = w * 4;
        #pragma unroll 4
        for (int k = 0; k < DIN; k++) {
            unsigned long long wv = Wsu[k * 32 + cp];
            a0 = ffma2(pack2dup(xs[r + 0][k]), wv, a0);
            a1 = ffma2(pack2dup(xs[r + 1][k]), wv, a1);
            a2 = ffma2(pack2dup(xs[r + 2][k]), wv, a2);
            a3 = ffma2(pack2dup(xs[r + 3][k]), wv, a3);
        }
        unsigned long long acc[4] = {a0, a1, a2, a3};
        #pragma unroll
        for (int j = 0; j < 4; j++) {
            int row = row0 + r + j;
            if (row < NN) *(float2*)&d_xl1[row * HIDN + (cp << 1)] = unpack2(acc[j]);
        }
    }
}

// ---------------- prep1: per-node attention logits ---------------------------
__global__ __launch_bounds__(256) void k_prep1(const float* __restrict__ a_src,
                                               const float* __restrict__ a_dst) {
    int gt = blockIdx.x * blockDim.x + threadIdx.x;
    if (gt >= NN * NHEAD) return;
    int n = gt >> 2, h = gt & 3;
    const float4* xr = (const float4*)(d_xl1 + n * HIDN + h * C1);
    const float4* as = (const float4*)(a_src + h * C1);
    const float4* ad = (const float4*)(a_dst + h * C1);
    float s = 0.f, d = 0.f;
    #pragma unroll
    for (int i = 0; i < 4; i++) {
        float4 v = xr[i], a = as[i], b = ad[i];
        s += v.x * a.x + v.y * a.y + v.z * a.z + v.w * a.w;
        d += v.x * b.x + v.y * b.y + v.z * b.z + v.w * b.w;
    }
    d_es1[gt] = s;
    d_ed1[gt] = d;
}

// ---------------- layer-1 GAT: warp per node, CSR gather, no atomics ---------
__global__ __launch_bounds__(256) void k_gat1() {
    int warp = (blockIdx.x * blockDim.x + threadIdx.x) >> 5;
    if (warp >= NN) return;
    int lane = threadIdx.x & 31;
    int n = warp;
    int start = d_off[n], end = d_off[n + 1];

    float edr0 = d_ed1[n * 4 + 0];
    float edr1 = d_ed1[n * 4 + 1];
    float edr2 = d_ed1[n * 4 + 2];
    float edr3 = d_ed1[n * 4 + 3];

    // pass 1: per-head max over in-edges (lane-strided)
    float m0 = NEG_INF(), m1 = m0, m2 = m0, m3 = m0;
    for (int j = start + lane; j < end; j += 32) {
        int s = d_csrc[j];
        float4 es = *(const float4*)&d_es1[s * 4];
        m0 = fmaxf(m0, lrelu(es.x + edr0));
        m1 = fmaxf(m1, lrelu(es.y + edr1));
        m2 = fmaxf(m2, lrelu(es.z + edr2));
        m3 = fmaxf(m3, lrelu(es.w + edr3));
    }
    #pragma unroll
    for (int o = 16; o > 0; o >>= 1) {
        m0 = fmaxf(m0, __shfl_xor_sync(0xffffffffu, m0, o));
        m1 = fmaxf(m1, __shfl_xor_sync(0xffffffffu, m1, o));
        m2 = fmaxf(m2, __shfl_xor_sync(0xffffffffu, m2, o));
        m3 = fmaxf(m3, __shfl_xor_sync(0xffffffffu, m3, o));
    }

    // pass 2: each lane owns cols (lane) head h0 and (lane+32) head h0+2
    int h0 = lane >> 4;                  // 0 or 1
    float mA  = h0 ? m1 : m0;
    float mB  = h0 ? m3 : m2;
    float edA = h0 ? edr1 : edr0;
    float edB = h0 ? edr3 : edr2;

    float acc0 = 0.f, acc1 = 0.f, sA = 0.f, sB = 0.f;
    for (int j = start; j < end; j++) {
        int s = d_csrc[j];               // broadcast across warp
        float eA = lrelu(d_es1[s * 4 + h0]     + edA);
        float eB = lrelu(d_es1[s * 4 + h0 + 2] + edB);
        float pA = __expf(eA - mA);
        float pB = __expf(eB - mB);
        sA += pA; sB += pB;
        acc0 += pA * d_xl1[s * HIDN + lane];
        acc1 += pB * d_xl1[s * HIDN + 32 + lane];
    }
    d_h1[n * HIDN + lane]      = acc0 / (sA + 1e-16f);
    d_h1[n * HIDN + 32 + lane] = acc1 / (sB + 1e-16f);
}

// ---------------- batch-norm stats (generic) ---------------------------------
__global__ __launch_bounds__(256) void k_bn_stats(const float* __restrict__ data,
                                                  float* __restrict__ stats,
                                                  int ncols, int total) {
    int tid = blockIdx.x * blockDim.x + threadIdx.x;
    int nth = gridDim.x * blockDim.x;
    float s = 0.f, ss = 0.f;
    for (int i = tid; i < total; i += nth) {
        float v = data[i];
        s += v; ss += v * v;
    }
    int col = tid % ncols;
    atomicAdd(&stats[col], s);
    atomicAdd(&stats[ncols + col], ss);
}

__global__ __launch_bounds__(256) void k_bn_apply1(const float* __restrict__ g1,
                                                   const float* __restrict__ be1) {
    int i = blockIdx.x * blockDim.x + threadIdx.x;
    if (i >= NN * HIDN) return;
    int col = i & 63;
    float mu  = d_stats1[col] * (1.0f / NN);
    float var = d_stats1[HIDN + col] * (1.0f / NN) - mu * mu;
    float v = (d_h1[i] - mu) * rsqrtf(var + BN_EPS) * g1[col] + be1[col];
    d_h1[i] = fmaxf(v, 0.f);
}

// ---------------- GEMM2: xl2 = h1 @ W2  ([N,64]@[64,32]) ---------------------
__global__ __launch_bounds__(256) void k_gemm2(const float* __restrict__ W2) {
    __shared__ float Ws[HIDN * OUTC];   // 8 KB
    __shared__ float xs[8][HIDN];
    int tid = threadIdx.x;
    for (int i = tid; i < HIDN * OUTC; i += 256) Ws[i] = W2[i];
    int col = tid & 31;
    int r   = tid >> 5;
    for (int row0 = blockIdx.x * 8; row0 < NN; row0 += gridDim.x * 8) {
        __syncthreads();
        for (int i = tid; i < 8 * HIDN; i += 256) {
            int rr = i >> 6, k = i & 63;
            int row = row0 + rr;
            xs[rr][k] = (row < NN) ? d_h1[row * HIDN + k] : 0.f;
        }
        __syncthreads();
        int row = row0 + r;
        if (row < NN) {
            float acc = 0.f;
            #pragma unroll
            for (int k = 0; k < HIDN; k++) acc = fmaf(xs[r][k], Ws[k * OUTC + col], acc);
            d_xl2[row * OUTC + col] = acc;
        }
    }
}

// ---------------- prep2: warp per node ---------------------------------------
__global__ __launch_bounds__(256) void k_prep2(const float* __restrict__ a_src,
                                               const float* __restrict__ a_dst) {
    int gt = blockIdx.x * blockDim.x + threadIdx.x;
    if (gt >= NN * 32) return;
    int n = gt >> 5, lane = gt & 31;
    float v = d_xl2[n * OUTC + lane];
    float s = v * a_src[lane];
    float d = v * a_dst[lane];
    #pragma unroll
    for (int o = 16; o > 0; o >>= 1) {
        s += __shfl_xor_sync(0xffffffffu, s, o);
        d += __shfl_xor_sync(0xffffffffu, d, o);
    }
    if (lane == 0) { d_es2[n] = s; d_ed2[n] = d; }
}

// ---------------- layer-2 GAT: warp per node ---------------------------------
__global__ __launch_bounds__(256) void k_gat2() {
    int warp = (blockIdx.x * blockDim.x + threadIdx.x) >> 5;
    if (warp >= NN) return;
    int lane = threadIdx.x & 31;
    int n = warp;
    int start = d_off[n], end = d_off[n + 1];
    float ed = d_ed2[n];

    float m = NEG_INF();
    for (int j = start + lane; j < end; j += 32)
        m = fmaxf(m, lrelu(d_es2[d_csrc[j]] + ed));
    #pragma unroll
    for (int o = 16; o > 0; o >>= 1)
        m = fmaxf(m, __shfl_xor_sync(0xffffffffu, m, o));

    float acc = 0.f, ssum = 0.f;
    for (int j = start; j < end; j++) {
        int s = d_csrc[j];
        float p = __expf(lrelu(d_es2[s] + ed) - m);
        ssum += p;
        acc += p * d_xl2[s * OUTC + lane];
    }
    d_h2[n * OUTC + lane] = acc / (ssum + 1e-16f);
}

// ---------------- BN2 + write node_emb + pooling -----------------------------
__global__ __launch_bounds__(256) void k_bn2_pool(const float* __restrict__ g2,
                                                  const float* __restrict__ be2,
                                                  const int* __restrict__ batch,
                                                  float* __restrict__ out) {
    int i = blockIdx.x * blockDim.x + threadIdx.x;
    if (i >= NN * OUTC) return;
    int col = i & 31, n = i >> 5;
    float mu  = d_stats2[col] * (1.0f / NN);
    float var = d_stats2[OUTC + col] * (1.0f / NN) - mu * mu;
    float v = (d_h2[i] - mu) * rsqrtf(var + BN_EPS) * g2[col] + be2[col];
    out[i] = v;
    int b = batch[n];
    atomicAdd(&d_gsum[b * OUTC + col], v);
    atomicMaxF(&d_gmax[b * OUTC + col], v);
    if (col == 0) atomicAdd(&d_gcnt[b], 1.f);
}

// ---------------- final MLP over graph embeddings ----------------------------
__global__ __launch_bounds__(256) void k_final(const float* __restrict__ fcW1,
                                               const float* __restrict__ fcb1,
                                               const float* __restrict__ fcW2,
                                               const float* __restrict__ fcb2,
                                               float* __restrict__ out) {
    __shared__ float g[NB * 2 * OUTC];
    __shared__ float t[NB * OUTC];
    int tid = threadIdx.x;
    for (int i = tid; i < NB * 2 * OUTC; i += 256) {
        int b = i >> 6, j = i & 63;
        float v;
        if (j < OUTC) {
            v = d_gsum[b * OUTC + j] / fmaxf(d_gcnt[b], 1.f);
        } else {
            v = d_gmax[b * OUTC + (j - OUTC)];
            if (v < -3e37f) v = 0.f;
        }
        g[i] = v;
    }
    __syncthreads();
    for (int i = tid; i < NB * OUTC; i += 256) {
        int b = i >> 5, o = i & 31;
        float acc = fcb1[o];
        #pragma unroll
        for (int j = 0; j < 2 * OUTC; j++) acc = fmaf(g[b * 64 + j], fcW1[j * OUTC + o], acc);
        t[i] = fmaxf(acc, 0.f);
    }
    __syncthreads();
    for (int i = tid; i < NB * OUTC; i += 256) {
        int b = i >> 5, o = i & 31;
        float acc = fcb2[o];
        #pragma unroll
        for (int j = 0; j < OUTC; j++) acc = fmaf(t[b * OUTC + j], fcW2[j * OUTC + o], acc);
        out[NN * OUTC + i] = acc;
    }
}

// =============================================================================
extern "C" void kernel_launch(void* const* d_in, const int* in_sizes, int n_in,
                              void* d_out, int out_size) {
    const float* x      = (const float*)d_in[0];
    const int*   ei     = (const int*)  d_in[1];
    const int*   batch  = (const int*)  d_in[2];
    const float* W1     = (const float*)d_in[3];
    const float* a_src1 = (const float*)d_in[4];
    const float* a_dst1 = (const float*)d_in[5];
    const float* g1     = (const float*)d_in[7];
    const float* be1    = (const float*)d_in[8];
    const float* W2     = (const float*)d_in[9];
    const float* a_src2 = (const float*)d_in[10];
    const float* a_dst2 = (const float*)d_in[11];
    const float* g2     = (const float*)d_in[13];
    const float* be2    = (const float*)d_in[14];
    const float* fcW1   = (const float*)d_in[15];
    const float* fcb1   = (const float*)d_in[16];
    const float* fcW2   = (const float*)d_in[17];
    const float* fcb2   = (const float*)d_in[18];
    float* out = (float*)d_out;

    float* p_h1;  cudaGetSymbolAddress((void**)&p_h1,  d_h1);
    float* p_st1; cudaGetSymbolAddress((void**)&p_st1, d_stats1);
    float* p_h2;  cudaGetSymbolAddress((void**)&p_h2,  d_h2);
    float* p_st2; cudaGetSymbolAddress((void**)&p_st2, d_stats2);

    // CSR build (also zero-inits stats/pool scratch)
    k_deg_init<<<(NN + 255) / 256, 256>>>();
    k_deg_count<<<(EE + 255) / 256, 256>>>(ei);
    k_scan<<<1, 1024>>>();
    k_fill<<<(ET + 255) / 256, 256>>>(ei);

    // layer 1
    k_gemm1<<<(NN + 31) / 32, 256>>>(x, W1);
    k_prep1<<<(NN * NHEAD + 255) / 256, 256>>>(a_src1, a_dst1);
    k_gat1<<<(NN * 32 + 255) / 256, 256>>>();
    k_bn_stats<<<64, 256>>>(p_h1, p_st1, HIDN, NN * HIDN);
    k_bn_apply1<<<(NN * HIDN + 255) / 256, 256>>>(g1, be1);

    // layer 2
    k_gemm2<<<592, 256>>>(W2);
    k_prep2<<<(NN * 32 + 255) / 256, 256>>>(a_src2, a_dst2);
    k_gat2<<<(NN * 32 + 255) / 256, 256>>>();
    k_bn_stats<<<64, 256>>>(p_h2, p_st2, OUTC, NN * OUTC);
    k_bn2_pool<<<(NN * OUTC + 255) / 256, 256>>>(g2, be2, batch, out);

    // graph head
    k_final<<<1, 256>>>(fcW1, fcb1, fcW2, fcb2, out);
}

// round 4
// speedup vs baseline: 1.5973x; 1.0253x over previous
#include <cuda_runtime.h>
#include <cuda_bf16.h>

#define NN   50000
#define EE   800000
#define ET   (EE + NN)      // edges + self loops = 850000
#define DIN  128
#define HIDN 64
#define OUTC 32
#define NB   64
#define NHEAD 4
#define C1   16

#define NEG_SLOPE 0.2f
#define BN_EPS 1e-5f

// ---------------- scratch ----------------------------------------------------
__device__ float d_xl1[NN * HIDN];
__device__ float d_es1[NN * NHEAD];
__device__ float d_ed1[NN * NHEAD];
__device__ float d_h1[NN * HIDN];
__device__ float d_stats1[2 * HIDN];

__device__ float d_xl2[NN * OUTC];
__device__ float d_es2[NN];
__device__ float d_ed2[NN];
__device__ float d_h2[NN * OUTC];
__device__ float d_stats2[2 * OUTC];

__device__ float d_gsum[NB * OUTC];
__device__ float d_gmax[NB * OUTC];
__device__ float d_gcnt[NB];

// CSR (by dst)
__device__ int d_deg[NN];
__device__ int d_off[NN + 1];
__device__ int d_cursor[NN];
__device__ int d_csrc[ET];

__device__ __forceinline__ float NEG_INF() { return __int_as_float(0xff800000); }

__device__ __forceinline__ void atomicMaxF(float* addr, float v) {
    if (v >= 0.0f) atomicMax((int*)addr, __float_as_int(v));
    else           atomicMin((unsigned int*)addr, __float_as_uint(v));
}

__device__ __forceinline__ float lrelu(float e) { return e > 0.f ? e : NEG_SLOPE * e; }

// packed f32x2 helpers (sm_100+)
__device__ __forceinline__ unsigned long long pack2dup(float x) {
    unsigned long long r;
    asm("mov.b64 %0, {%1,%2};" : "=l"(r) : "f"(x), "f"(x));
    return r;
}
__device__ __forceinline__ unsigned long long ffma2(unsigned long long a,
                                                    unsigned long long b,
                                                    unsigned long long c) {
    unsigned long long d;
    asm("fma.rn.f32x2 %0, %1, %2, %3;" : "=l"(d) : "l"(a), "l"(b), "l"(c));
    return d;
}
__device__ __forceinline__ float2 unpack2(unsigned long long v) {
    float2 f;
    asm("mov.b64 {%0,%1}, %2;" : "=f"(f.x), "=f"(f.y) : "l"(v));
    return f;
}

// ---------------- init + CSR build -------------------------------------------
__global__ __launch_bounds__(256) void k_deg_init() {
    int i = blockIdx.x * blockDim.x + threadIdx.x;
    if (i >= NN) return;
    d_deg[i] = 1;                       // self loop
    if (i < 2 * HIDN) d_stats1[i] = 0.f;
    if (i < 2 * OUTC) d_stats2[i] = 0.f;
    if (i < NB * OUTC) { d_gsum[i] = 0.f; d_gmax[i] = NEG_INF(); }
    if (i < NB) d_gcnt[i] = 0.f;
}

__global__ __launch_bounds__(256) void k_deg_count(const int* __restrict__ ei) {
    int i0 = (blockIdx.x * blockDim.x + threadIdx.x) * 4;
    #pragma unroll
    for (int r = 0; r < 4; r++) {
        int i = i0 + r;
        if (i < EE) atomicAdd(&d_deg[ei[EE + i]], 1);
    }
}

__global__ __launch_bounds__(1024) void k_scan() {
    __shared__ int part[1024];
    const int CH = (NN + 1023) / 1024;
    int t = threadIdx.x;
    int base = t * CH;
    int lim = min(base + CH, NN);
    int s = 0;
    for (int i = base; i < lim; i++) s += d_deg[i];
    part[t] = s;
    __syncthreads();
    for (int off = 1; off < 1024; off <<= 1) {
        int v = (t >= off) ? part[t - off] : 0;
        __syncthreads();
        part[t] += v;
        __syncthreads();
    }
    int run = (t == 0) ? 0 : part[t - 1];
    for (int i = base; i < lim; i++) {
        d_off[i] = run;
        d_cursor[i] = run;
        run += d_deg[i];
    }
    if (t == 0) d_off[NN] = part[1023];
}

__global__ __launch_bounds__(256) void k_fill(const int* __restrict__ ei) {
    int i0 = (blockIdx.x * blockDim.x + threadIdx.x) * 4;
    #pragma unroll
    for (int r = 0; r < 4; r++) {
        int i = i0 + r;
        if (i >= ET) continue;
        int src, dst;
        if (i < EE) { src = ei[i]; dst = ei[EE + i]; } else { src = dst = i - EE; }
        int pos = atomicAdd(&d_cursor[dst], 1);
        d_csrc[pos] = src;
    }
}

// ---------------- GEMM1 + fused prep1 ----------------------------------------
__global__ __launch_bounds__(256) void k_gemm1(const float* __restrict__ x,
                                               const float* __restrict__ W1,
                                               const float* __restrict__ a_src,
                                               const float* __restrict__ a_dst) {
    __shared__ float2 Ws2[DIN * 32];    // 32 KB
    __shared__ float  xs[32][DIN];      // 16 KB
    __shared__ float  sa_s[HIDN], sd_s[HIDN];
    int tid = threadIdx.x;
    for (int i = tid; i < DIN * 32; i += 256) {
        int k = i >> 5, cp = i & 31;
        Ws2[i] = *(const float2*)&W1[k * HIDN + (cp << 1)];
    }
    if (tid < HIDN) { sa_s[tid] = a_src[tid]; sd_s[tid] = a_dst[tid]; }
    const unsigned long long* Wsu = (const unsigned long long*)Ws2;
    int cp = tid & 31;
    int w  = tid >> 5;
    float wa0 = 0.f, wa1 = 0.f, wd0 = 0.f, wd1 = 0.f;   // set after sync
    for (int row0 = blockIdx.x * 32; row0 < NN; row0 += gridDim.x * 32) {
        __syncthreads();
        if (row0 == blockIdx.x * 32) {  // first iter: a vectors now valid
            wa0 = sa_s[2 * cp]; wa1 = sa_s[2 * cp + 1];
            wd0 = sd_s[2 * cp]; wd1 = sd_s[2 * cp + 1];
        }
        for (int i = tid; i < 32 * DIN / 4; i += 256) {
            int rr = i >> 5, k4 = i & 31;
            int row = row0 + rr;
            ((float4*)xs[rr])[k4] = (row < NN) ? ((const float4*)(x + row * DIN))[k4]
                                               : make_float4(0.f, 0.f, 0.f, 0.f);
        }
        __syncthreads();
        unsigned long long a0 = 0ull, a1 = 0ull, a2 = 0ull, a3 = 0ull;
        int r = w * 4;
        #pragma unroll 4
        for (int k = 0; k < DIN; k++) {
            unsigned long long wv = Wsu[k * 32 + cp];
            a0 = ffma2(pack2dup(xs[r + 0][k]), wv, a0);
            a1 = ffma2(pack2dup(xs[r + 1][k]), wv, a1);
            a2 = ffma2(pack2dup(xs[r + 2][k]), wv, a2);
            a3 = ffma2(pack2dup(xs[r + 3][k]), wv, a3);
        }
        unsigned long long acc[4] = {a0, a1, a2, a3};
        #pragma unroll
        for (int j = 0; j < 4; j++) {
            int row = row0 + r + j;
            if (row >= NN) continue;
            float2 v = unpack2(acc[j]);
            *(float2*)&d_xl1[row * HIDN + (cp << 1)] = v;
            // fused prep1: es/ed per head (8-lane segmented reduce)
            float sa = v.x * wa0 + v.y * wa1;
            float sd = v.x * wd0 + v.y * wd1;
            #pragma unroll
            for (int o = 4; o > 0; o >>= 1) {
                sa += __shfl_xor_sync(0xffffffffu, sa, o);
                sd += __shfl_xor_sync(0xffffffffu, sd, o);
            }
            if ((cp & 7) == 0) {
                int h = cp >> 3;
                d_es1[row * 4 + h] = sa;
                d_ed1[row * 4 + h] = sd;
            }
        }
    }
}

// ---------------- layer-1 GAT (no max pass) + fused BN1 stats ----------------
__global__ __launch_bounds__(256) void k_gat1() {
    __shared__ float s_sum[HIDN], s_sq[HIDN];
    int tid = threadIdx.x;
    int lane = tid & 31, w = tid >> 5;
    if (tid < HIDN) { s_sum[tid] = 0.f; s_sq[tid] = 0.f; }
    __syncthreads();
    int h0 = lane >> 4;                  // 0 or 1
    for (int n = blockIdx.x * 8 + w; n < NN; n += gridDim.x * 8) {
        int start = d_off[n], end = d_off[n + 1];
        float4 ed = *(const float4*)&d_ed1[n * 4];
        float acc0 = 0.f, acc1 = 0.f;
        float s0 = 0.f, s1 = 0.f, s2 = 0.f, s3 = 0.f;
        for (int j0 = start; j0 < end; j0 += 32) {
            int j = j0 + lane;
            int cnt = min(32, end - j0);
            int s = 0;
            float p0 = 0.f, p1 = 0.f, p2 = 0.f, p3 = 0.f;
            if (j < end) {
                s = d_csrc[j];
                float4 es = *(const float4*)&d_es1[s * 4];
                p0 = __expf(lrelu(es.x + ed.x));
                p1 = __expf(lrelu(es.y + ed.y));
                p2 = __expf(lrelu(es.z + ed.z));
                p3 = __expf(lrelu(es.w + ed.w));
            }
            s0 += p0; s1 += p1; s2 += p2; s3 += p3;
            for (int t = 0; t < cnt; t++) {
                int   ss = __shfl_sync(0xffffffffu, s, t);
                float q0 = __shfl_sync(0xffffffffu, p0, t);
                float q1 = __shfl_sync(0xffffffffu, p1, t);
                float q2 = __shfl_sync(0xffffffffu, p2, t);
                float q3 = __shfl_sync(0xffffffffu, p3, t);
                float pA = h0 ? q1 : q0;
                float pB = h0 ? q3 : q2;
                acc0 += pA * d_xl1[ss * HIDN + lane];
                acc1 += pB * d_xl1[ss * HIDN + 32 + lane];
            }
        }
        #pragma unroll
        for (int o = 16; o > 0; o >>= 1) {
            s0 += __shfl_xor_sync(0xffffffffu, s0, o);
            s1 += __shfl_xor_sync(0xffffffffu, s1, o);
            s2 += __shfl_xor_sync(0xffffffffu, s2, o);
            s3 += __shfl_xor_sync(0xffffffffu, s3, o);
        }
        float sA = h0 ? s1 : s0;
        float sB = h0 ? s3 : s2;
        float v0 = acc0 / (sA + 1e-16f);
        float v1 = acc1 / (sB + 1e-16f);
        d_h1[n * HIDN + lane]      = v0;
        d_h1[n * HIDN + 32 + lane] = v1;
        atomicAdd(&s_sum[lane], v0);       atomicAdd(&s_sum[32 + lane], v1);
        atomicAdd(&s_sq[lane], v0 * v0);   atomicAdd(&s_sq[32 + lane], v1 * v1);
    }
    __syncthreads();
    if (tid < HIDN) {
        atomicAdd(&d_stats1[tid], s_sum[tid]);
        atomicAdd(&d_stats1[HIDN + tid], s_sq[tid]);
    }
}

// ---------------- GEMM2 (BN1 apply fused at load) + fused prep2 --------------
__global__ __launch_bounds__(256) void k_gemm2(const float* __restrict__ W2,
                                               const float* __restrict__ g1,
                                               const float* __restrict__ be1,
                                               const float* __restrict__ a_src2,
                                               const float* __restrict__ a_dst2) {
    __shared__ float Ws[HIDN * OUTC];   // 8 KB
    __shared__ float xs[8][HIDN];
    __shared__ float bnm[HIDN], bna[HIDN];
    int tid = threadIdx.x;
    for (int i = tid; i < HIDN * OUTC; i += 256) Ws[i] = W2[i];
    if (tid < HIDN) {
        float mu  = d_stats1[tid] * (1.0f / NN);
        float var = d_stats1[HIDN + tid] * (1.0f / NN) - mu * mu;
        float m = rsqrtf(var + BN_EPS) * g1[tid];
        bnm[tid] = m;
        bna[tid] = be1[tid] - mu * m;
    }
    int col = tid & 31;
    int r   = tid >> 5;
    float a2s = a_src2[col], a2d = a_dst2[col];
    for (int row0 = blockIdx.x * 8; row0 < NN; row0 += gridDim.x * 8) {
        __syncthreads();
        for (int i = tid; i < 8 * HIDN; i += 256) {
            int rr = i >> 6, k = i & 63;
            int row = row0 + rr;
            float hv = (row < NN) ? d_h1[row * HIDN + k] : 0.f;
            xs[rr][k] = fmaxf(fmaf(hv, bnm[k], bna[k]), 0.f);   // BN+ReLU fused
        }
        __syncthreads();
        int row = row0 + r;
        if (row < NN) {
            float acc = 0.f;
            #pragma unroll
            for (int k = 0; k < HIDN; k++) acc = fmaf(xs[r][k], Ws[k * OUTC + col], acc);
            d_xl2[row * OUTC + col] = acc;
            // fused prep2: warp reduce
            float es = acc * a2s, edv = acc * a2d;
            #pragma unroll
            for (int o = 16; o > 0; o >>= 1) {
                es  += __shfl_xor_sync(0xffffffffu, es, o);
                edv += __shfl_xor_sync(0xffffffffu, edv, o);
            }
            if (col == 0) { d_es2[row] = es; d_ed2[row] = edv; }
        }
    }
}

// ---------------- layer-2 GAT (no max pass) + fused BN2 stats ----------------
__global__ __launch_bounds__(256) void k_gat2() {
    __shared__ float s_sum[OUTC], s_sq[OUTC];
    int tid = threadIdx.x;
    int lane = tid & 31, w = tid >> 5;
    if (tid < OUTC) { s_sum[tid] = 0.f; s_sq[tid] = 0.f; }
    __syncthreads();
    for (int n = blockIdx.x * 8 + w; n < NN; n += gridDim.x * 8) {
        int start = d_off[n], end = d_off[n + 1];
        float ed = d_ed2[n];
        float acc = 0.f, psum = 0.f;
        for (int j0 = start; j0 < end; j0 += 32) {
            int j = j0 + lane;
            int cnt = min(32, end - j0);
            int s = 0;
            float p = 0.f;
            if (j < end) {
                s = d_csrc[j];
                p = __expf(lrelu(d_es2[s] + ed));
            }
            psum += p;
            for (int t = 0; t < cnt; t++) {
                int   ss = __shfl_sync(0xffffffffu, s, t);
                float pp = __shfl_sync(0xffffffffu, p, t);
                acc += pp * d_xl2[ss * OUTC + lane];
            }
        }
        #pragma unroll
        for (int o = 16; o > 0; o >>= 1)
            psum += __shfl_xor_sync(0xffffffffu, psum, o);
        float v = acc / (psum + 1e-16f);
        d_h2[n * OUTC + lane] = v;
        atomicAdd(&s_sum[lane], v);
        atomicAdd(&s_sq[lane], v * v);
    }
    __syncthreads();
    if (tid < OUTC) {
        atomicAdd(&d_stats2[tid], s_sum[tid]);
        atomicAdd(&d_stats2[OUTC + tid], s_sq[tid]);
    }
}

// ---------------- BN2 + node_emb + pooling -----------------------------------
__global__ __launch_bounds__(256) void k_bn2_pool(const float* __restrict__ g2,
                                                  const float* __restrict__ be2,
                                                  const int* __restrict__ batch,
                                                  float* __restrict__ out) {
    int i = blockIdx.x * blockDim.x + threadIdx.x;
    if (i >= NN * OUTC) return;
    int col = i & 31, n = i >> 5;
    float mu  = d_stats2[col] * (1.0f / NN);
    float var = d_stats2[OUTC + col] * (1.0f / NN) - mu * mu;
    float v = (d_h2[i] - mu) * rsqrtf(var + BN_EPS) * g2[col] + be2[col];
    out[i] = v;
    int b = batch[n];
    atomicAdd(&d_gsum[b * OUTC + col], v);
    atomicMaxF(&d_gmax[b * OUTC + col], v);
    if (col == 0) atomicAdd(&d_gcnt[b], 1.f);
}

// ---------------- final MLP ---------------------------------------------------
__global__ __launch_bounds__(256) void k_final(const float* __restrict__ fcW1,
                                               const float* __restrict__ fcb1,
                                               const float* __restrict__ fcW2,
                                               const float* __restrict__ fcb2,
                                               float* __restrict__ out) {
    __shared__ float g[NB * 2 * OUTC];
    __shared__ float t[NB * OUTC];
    int tid = threadIdx.x;
    for (int i = tid; i < NB * 2 * OUTC; i += 256) {
        int b = i >> 6, j = i & 63;
        float v;
        if (j < OUTC) {
            v = d_gsum[b * OUTC + j] / fmaxf(d_gcnt[b], 1.f);
        } else {
            v = d_gmax[b * OUTC + (j - OUTC)];
            if (v < -3e37f) v = 0.f;
        }
        g[i] = v;
    }
    __syncthreads();
    for (int i = tid; i < NB * OUTC; i += 256) {
        int b = i >> 5, o = i & 31;
        float acc = fcb1[o];
        #pragma unroll
        for (int j = 0; j < 2 * OUTC; j++) acc = fmaf(g[b * 64 + j], fcW1[j * OUTC + o], acc);
        t[i] = fmaxf(acc, 0.f);
    }
    __syncthreads();
    for (int i = tid; i < NB * OUTC; i += 256) {
        int b = i >> 5, o = i & 31;
        float acc = fcb2[o];
        #pragma unroll
        for (int j = 0; j < OUTC; j++) acc = fmaf(t[b * OUTC + j], fcW2[j * OUTC + o], acc);
        out[NN * OUTC + i] = acc;
    }
}

// =============================================================================
extern "C" void kernel_launch(void* const* d_in, const int* in_sizes, int n_in,
                              void* d_out, int out_size) {
    const float* x      = (const float*)d_in[0];
    const int*   ei     = (const int*)  d_in[1];
    const int*   batch  = (const int*)  d_in[2];
    const float* W1     = (const float*)d_in[3];
    const float* a_src1 = (const float*)d_in[4];
    const float* a_dst1 = (const float*)d_in[5];
    const float* g1     = (const float*)d_in[7];
    const float* be1    = (const float*)d_in[8];
    const float* W2     = (const float*)d_in[9];
    const float* a_src2 = (const float*)d_in[10];
    const float* a_dst2 = (const float*)d_in[11];
    const float* g2     = (const float*)d_in[13];
    const float* be2    = (const float*)d_in[14];
    const float* fcW1   = (const float*)d_in[15];
    const float* fcb1   = (const float*)d_in[16];
    const float* fcW2   = (const float*)d_in[17];
    const float* fcb2   = (const float*)d_in[18];
    float* out = (float*)d_out;

    // CSR build (also zero-inits stats/pool scratch)
    k_deg_init<<<(NN + 255) / 256, 256>>>();
    k_deg_count<<<(EE / 4 + 255) / 256, 256>>>(ei);
    k_scan<<<1, 1024>>>();
    k_fill<<<(ET / 4 + 256) / 256, 256>>>(ei);

    // layer 1
    k_gemm1<<<(NN + 31) / 32, 256>>>(x, W1, a_src1, a_dst1);
    k_gat1<<<592, 256>>>();

    // layer 2
    k_gemm2<<<592, 256>>>(W2, g1, be1, a_src2, a_dst2);
    k_gat2<<<592, 256>>>();
    k_bn2_pool<<<(NN * OUTC + 255) / 256, 256>>>(g2, be2, batch, out);

    // graph head
    k_final<<<1, 256>>>(fcW1, fcb1, fcW2, fcb2, out);
}

// round 5
// speedup vs baseline: 1.9685x; 1.2324x over previous
#include <cuda_runtime.h>
#include <cuda_bf16.h>

#define NN   50000
#define EE   800000
#define ET   (EE + NN)      // edges + self loops = 850000
#define DIN  128
#define HIDN 64
#define OUTC 32
#define NB   64
#define NHEAD 4
#define C1   16

#define NEG_SLOPE 0.2f
#define BN_EPS 1e-5f

// ---------------- scratch ----------------------------------------------------
// xl1 stored PAIRED: element [n][c] = float2( col c, col c+32 ), c in 0..31
__device__ float2 d_xl1p[NN * 32];
__device__ float d_es1[NN * NHEAD];
__device__ float d_ed1[NN * NHEAD];
__device__ float d_h1[NN * HIDN];
__device__ float d_stats1[2 * HIDN];

__device__ float d_xl2[NN * OUTC];
__device__ float d_es2[NN];
__device__ float d_ed2[NN];
__device__ float d_h2[NN * OUTC];
__device__ float d_stats2[2 * OUTC];

__device__ float d_gsum[NB * OUTC];
__device__ float d_gmax[NB * OUTC];
__device__ float d_gcnt[NB];

// CSR (by dst)
__device__ int d_deg[NN];
__device__ int d_off[NN + 1];
__device__ int d_cursor[NN];
__device__ int d_csrc[ET];

__device__ __forceinline__ float NEG_INF() { return __int_as_float(0xff800000); }

__device__ __forceinline__ void atomicMaxF(float* addr, float v) {
    if (v >= 0.0f) atomicMax((int*)addr, __float_as_int(v));
    else           atomicMin((unsigned int*)addr, __float_as_uint(v));
}

__device__ __forceinline__ float lrelu(float e) { return e > 0.f ? e : NEG_SLOPE * e; }

// packed f32x2 helpers (sm_100+)
__device__ __forceinline__ unsigned long long pack2dup(float x) {
    unsigned long long r;
    asm("mov.b64 %0, {%1,%2};" : "=l"(r) : "f"(x), "f"(x));
    return r;
}
__device__ __forceinline__ unsigned long long ffma2(unsigned long long a,
                                                    unsigned long long b,
                                                    unsigned long long c) {
    unsigned long long d;
    asm("fma.rn.f32x2 %0, %1, %2, %3;" : "=l"(d) : "l"(a), "l"(b), "l"(c));
    return d;
}
__device__ __forceinline__ float2 unpack2(unsigned long long v) {
    float2 f;
    asm("mov.b64 {%0,%1}, %2;" : "=f"(f.x), "=f"(f.y) : "l"(v));
    return f;
}

// ---------------- init + CSR build -------------------------------------------
__global__ __launch_bounds__(256) void k_deg_init() {
    int i = blockIdx.x * blockDim.x + threadIdx.x;
    if (i >= NN) return;
    d_deg[i] = 1;                       // self loop
    if (i < 2 * HIDN) d_stats1[i] = 0.f;
    if (i < 2 * OUTC) d_stats2[i] = 0.f;
    if (i < NB * OUTC) { d_gsum[i] = 0.f; d_gmax[i] = NEG_INF(); }
    if (i < NB) d_gcnt[i] = 0.f;
}

__global__ __launch_bounds__(256) void k_deg_count(const int* __restrict__ ei) {
    int i0 = (blockIdx.x * blockDim.x + threadIdx.x) * 4;
    #pragma unroll
    for (int r = 0; r < 4; r++) {
        int i = i0 + r;
        if (i < EE) atomicAdd(&d_deg[ei[EE + i]], 1);
    }
}

__global__ __launch_bounds__(1024) void k_scan() {
    __shared__ int part[1024];
    const int CH = (NN + 1023) / 1024;
    int t = threadIdx.x;
    int base = t * CH;
    int lim = min(base + CH, NN);
    int s = 0;
    for (int i = base; i < lim; i++) s += d_deg[i];
    part[t] = s;
    __syncthreads();
    for (int off = 1; off < 1024; off <<= 1) {
        int v = (t >= off) ? part[t - off] : 0;
        __syncthreads();
        part[t] += v;
        __syncthreads();
    }
    int run = (t == 0) ? 0 : part[t - 1];
    for (int i = base; i < lim; i++) {
        d_off[i] = run;
        d_cursor[i] = run;
        run += d_deg[i];
    }
    if (t == 0) d_off[NN] = part[1023];
}

__global__ __launch_bounds__(256) void k_fill(const int* __restrict__ ei) {
    int i0 = (blockIdx.x * blockDim.x + threadIdx.x) * 4;
    #pragma unroll
    for (int r = 0; r < 4; r++) {
        int i = i0 + r;
        if (i >= ET) continue;
        int src, dst;
        if (i < EE) { src = ei[i]; dst = ei[EE + i]; } else { src = dst = i - EE; }
        int pos = atomicAdd(&d_cursor[dst], 1);
        d_csrc[pos] = src;
    }
}

// ---------------- GEMM1 + fused prep1 (paired output layout) -----------------
__global__ __launch_bounds__(256) void k_gemm1(const float* __restrict__ x,
                                               const float* __restrict__ W1,
                                               const float* __restrict__ a_src,
                                               const float* __restrict__ a_dst) {
    __shared__ float2 Ws2[DIN * 32];    // 32 KB: [k][cp] = (W[k][cp], W[k][cp+32])
    __shared__ float  xs[32][DIN];      // 16 KB
    __shared__ float  sa_s[HIDN], sd_s[HIDN];
    int tid = threadIdx.x;
    for (int i = tid; i < DIN * 32; i += 256) {
        int k = i >> 5, cp = i & 31;
        Ws2[i] = make_float2(W1[k * HIDN + cp], W1[k * HIDN + cp + 32]);
    }
    if (tid < HIDN) { sa_s[tid] = a_src[tid]; sd_s[tid] = a_dst[tid]; }
    const unsigned long long* Wsu = (const unsigned long long*)Ws2;
    int cp = tid & 31;
    int w  = tid >> 5;
    int h0 = cp >> 4;                     // head of col cp (0/1); col cp+32 -> h0+2
    float wa0 = 0.f, wa1 = 0.f, wd0 = 0.f, wd1 = 0.f;
    for (int row0 = blockIdx.x * 32; row0 < NN; row0 += gridDim.x * 32) {
        __syncthreads();
        if (row0 == blockIdx.x * 32) {
            wa0 = sa_s[cp]; wa1 = sa_s[cp + 32];
            wd0 = sd_s[cp]; wd1 = sd_s[cp + 32];
        }
        for (int i = tid; i < 32 * DIN / 4; i += 256) {
            int rr = i >> 5, k4 = i & 31;
            int row = row0 + rr;
            ((float4*)xs[rr])[k4] = (row < NN) ? ((const float4*)(x + row * DIN))[k4]
                                               : make_float4(0.f, 0.f, 0.f, 0.f);
        }
        __syncthreads();
        unsigned long long a0 = 0ull, a1 = 0ull, a2 = 0ull, a3 = 0ull;
        int r = w * 4;
        #pragma unroll 4
        for (int k = 0; k < DIN; k++) {
            unsigned long long wv = Wsu[k * 32 + cp];
            a0 = ffma2(pack2dup(xs[r + 0][k]), wv, a0);
            a1 = ffma2(pack2dup(xs[r + 1][k]), wv, a1);
            a2 = ffma2(pack2dup(xs[r + 2][k]), wv, a2);
            a3 = ffma2(pack2dup(xs[r + 3][k]), wv, a3);
        }
        unsigned long long acc[4] = {a0, a1, a2, a3};
        #pragma unroll
        for (int j = 0; j < 4; j++) {
            int row = row0 + r + j;
            if (row >= NN) continue;
            float2 v = unpack2(acc[j]);
            d_xl1p[row * 32 + cp] = v;
            // fused prep1: head sums. v.x -> head h0, v.y -> head h0+2.
            // 16-lane groups share h0 (lanes 0-15: h0=0; 16-31: h0=1).
            float sax = v.x * wa0, say = v.y * wa1;
            float sdx = v.x * wd0, sdy = v.y * wd1;
            #pragma unroll
            for (int o = 8; o > 0; o >>= 1) {
                sax += __shfl_xor_sync(0xffffffffu, sax, o);
                say += __shfl_xor_sync(0xffffffffu, say, o);
                sdx += __shfl_xor_sync(0xffffffffu, sdx, o);
                sdy += __shfl_xor_sync(0xffffffffu, sdy, o);
            }
            if ((cp & 15) == 0) {
                d_es1[row * 4 + h0]     = sax;
                d_es1[row * 4 + h0 + 2] = say;
                d_ed1[row * 4 + h0]     = sdx;
                d_ed1[row * 4 + h0 + 2] = sdy;
            }
        }
    }
}

// ---------------- layer-1 GAT + fused BN1 stats ------------------------------
__global__ __launch_bounds__(256) void k_gat1() {
    __shared__ float s_sum[HIDN], s_sq[HIDN];
    int tid = threadIdx.x;
    int lane = tid & 31, w = tid >> 5;
    if (tid < HIDN) { s_sum[tid] = 0.f; s_sq[tid] = 0.f; }
    __syncthreads();
    int h0 = lane >> 4;                  // 0 or 1
    for (int n = blockIdx.x * 8 + w; n < NN; n += gridDim.x * 8) {
        int start = d_off[n], end = d_off[n + 1];
        float4 ed = *(const float4*)&d_ed1[n * 4];
        float acc0 = 0.f, acc1 = 0.f;
        float s0 = 0.f, s1 = 0.f, s2 = 0.f, s3 = 0.f;
        for (int j0 = start; j0 < end; j0 += 32) {
            int j = j0 + lane;
            int cnt = min(32, end - j0);
            int s = 0;
            float p0 = 0.f, p1 = 0.f, p2 = 0.f, p3 = 0.f;
            if (j < end) {
                s = d_csrc[j];
                float4 es = *(const float4*)&d_es1[s * 4];
                p0 = __expf(lrelu(es.x + ed.x));
                p1 = __expf(lrelu(es.y + ed.y));
                p2 = __expf(lrelu(es.z + ed.z));
                p3 = __expf(lrelu(es.w + ed.w));
            }
            s0 += p0; s1 += p1; s2 += p2; s3 += p3;
            int t = 0;
            for (; t + 4 <= cnt; t += 4) {      // 4-wide pipelined broadcast
                int ssb[4]; float pa[4], pb[4]; float2 f[4];
                #pragma unroll
                for (int u = 0; u < 4; u++) {
                    ssb[u] = __shfl_sync(0xffffffffu, s, t + u);
                    float q0 = __shfl_sync(0xffffffffu, p0, t + u);
                    float q1 = __shfl_sync(0xffffffffu, p1, t + u);
                    float q2 = __shfl_sync(0xffffffffu, p2, t + u);
                    float q3 = __shfl_sync(0xffffffffu, p3, t + u);
                    pa[u] = h0 ? q1 : q0;
                    pb[u] = h0 ? q3 : q2;
                }
                #pragma unroll
                for (int u = 0; u < 4; u++) f[u] = d_xl1p[ssb[u] * 32 + lane];
                #pragma unroll
                for (int u = 0; u < 4; u++) {
                    acc0 += pa[u] * f[u].x;
                    acc1 += pb[u] * f[u].y;
                }
            }
            for (; t < cnt; t++) {
                int   ss = __shfl_sync(0xffffffffu, s, t);
                float q0 = __shfl_sync(0xffffffffu, p0, t);
                float q1 = __shfl_sync(0xffffffffu, p1, t);
                float q2 = __shfl_sync(0xffffffffu, p2, t);
                float q3 = __shfl_sync(0xffffffffu, p3, t);
                float2 f = d_xl1p[ss * 32 + lane];
                acc0 += (h0 ? q1 : q0) * f.x;
                acc1 += (h0 ? q3 : q2) * f.y;
            }
        }
        #pragma unroll
        for (int o = 16; o > 0; o >>= 1) {
            s0 += __shfl_xor_sync(0xffffffffu, s0, o);
            s1 += __shfl_xor_sync(0xffffffffu, s1, o);
            s2 += __shfl_xor_sync(0xffffffffu, s2, o);
            s3 += __shfl_xor_sync(0xffffffffu, s3, o);
        }
        float sA = h0 ? s1 : s0;
        float sB = h0 ? s3 : s2;
        float v0 = acc0 / (sA + 1e-16f);   // col = lane
        float v1 = acc1 / (sB + 1e-16f);   // col = lane + 32
        d_h1[n * HIDN + lane]      = v0;
        d_h1[n * HIDN + 32 + lane] = v1;
        atomicAdd(&s_sum[lane], v0);       atomicAdd(&s_sum[32 + lane], v1);
        atomicAdd(&s_sq[lane], v0 * v0);   atomicAdd(&s_sq[32 + lane], v1 * v1);
    }
    __syncthreads();
    if (tid < HIDN) {
        atomicAdd(&d_stats1[tid], s_sum[tid]);
        atomicAdd(&d_stats1[HIDN + tid], s_sq[tid]);
    }
}

// ---------------- GEMM2 (BN1 apply fused) + fused prep2 ----------------------
__global__ __launch_bounds__(256) void k_gemm2(const float* __restrict__ W2,
                                               const float* __restrict__ g1,
                                               const float* __restrict__ be1,
                                               const float* __restrict__ a_src2,
                                               const float* __restrict__ a_dst2) {
    __shared__ float Ws[HIDN * OUTC];
    __shared__ float xs[8][HIDN];
    __shared__ float bnm[HIDN], bna[HIDN];
    int tid = threadIdx.x;
    for (int i = tid; i < HIDN * OUTC; i += 256) Ws[i] = W2[i];
    if (tid < HIDN) {
        float mu  = d_stats1[tid] * (1.0f / NN);
        float var = d_stats1[HIDN + tid] * (1.0f / NN) - mu * mu;
        float m = rsqrtf(var + BN_EPS) * g1[tid];
        bnm[tid] = m;
        bna[tid] = be1[tid] - mu * m;
    }
    int col = tid & 31;
    int r   = tid >> 5;
    float a2s = a_src2[col], a2d = a_dst2[col];
    for (int row0 = blockIdx.x * 8; row0 < NN; row0 += gridDim.x * 8) {
        __syncthreads();
        for (int i = tid; i < 8 * HIDN; i += 256) {
            int rr = i >> 6, k = i & 63;
            int row = row0 + rr;
            float hv = (row < NN) ? d_h1[row * HIDN + k] : 0.f;
            xs[rr][k] = fmaxf(fmaf(hv, bnm[k], bna[k]), 0.f);
        }
        __syncthreads();
        int row = row0 + r;
        if (row < NN) {
            float acc = 0.f;
            #pragma unroll
            for (int k = 0; k < HIDN; k++) acc = fmaf(xs[r][k], Ws[k * OUTC + col], acc);
            d_xl2[row * OUTC + col] = acc;
            float es = acc * a2s, edv = acc * a2d;
            #pragma unroll
            for (int o = 16; o > 0; o >>= 1) {
                es  += __shfl_xor_sync(0xffffffffu, es, o);
                edv += __shfl_xor_sync(0xffffffffu, edv, o);
            }
            if (col == 0) { d_es2[row] = es; d_ed2[row] = edv; }
        }
    }
}

// ---------------- layer-2 GAT + fused BN2 stats ------------------------------
__global__ __launch_bounds__(256) void k_gat2() {
    __shared__ float s_sum[OUTC], s_sq[OUTC];
    int tid = threadIdx.x;
    int lane = tid & 31, w = tid >> 5;
    if (tid < OUTC) { s_sum[tid] = 0.f; s_sq[tid] = 0.f; }
    __syncthreads();
    for (int n = blockIdx.x * 8 + w; n < NN; n += gridDim.x * 8) {
        int start = d_off[n], end = d_off[n + 1];
        float ed = d_ed2[n];
        float acc = 0.f, psum = 0.f;
        for (int j0 = start; j0 < end; j0 += 32) {
            int j = j0 + lane;
            int cnt = min(32, end - j0);
            int s = 0;
            float p = 0.f;
            if (j < end) {
                s = d_csrc[j];
                p = __expf(lrelu(d_es2[s] + ed));
            }
            psum += p;
            int t = 0;
            for (; t + 4 <= cnt; t += 4) {
                int ssb[4]; float pp[4], f[4];
                #pragma unroll
                for (int u = 0; u < 4; u++) {
                    ssb[u] = __shfl_sync(0xffffffffu, s, t + u);
                    pp[u]  = __shfl_sync(0xffffffffu, p, t + u);
                }
                #pragma unroll
                for (int u = 0; u < 4; u++) f[u] = d_xl2[ssb[u] * OUTC + lane];
                #pragma unroll
                for (int u = 0; u < 4; u++) acc += pp[u] * f[u];
            }
            for (; t < cnt; t++) {
                int   ss = __shfl_sync(0xffffffffu, s, t);
                float pp = __shfl_sync(0xffffffffu, p, t);
                acc += pp * d_xl2[ss * OUTC + lane];
            }
        }
        #pragma unroll
        for (int o = 16; o > 0; o >>= 1)
            psum += __shfl_xor_sync(0xffffffffu, psum, o);
        float v = acc / (psum + 1e-16f);
        d_h2[n * OUTC + lane] = v;
        atomicAdd(&s_sum[lane], v);
        atomicAdd(&s_sq[lane], v * v);
    }
    __syncthreads();
    if (tid < OUTC) {
        atomicAdd(&d_stats2[tid], s_sum[tid]);
        atomicAdd(&d_stats2[OUTC + tid], s_sq[tid]);
    }
}

// ---------------- BN2 + node_emb + pooling (smem-accumulated) ----------------
#define PB_NODES 256
__global__ __launch_bounds__(256) void k_bn2_pool(const float* __restrict__ g2,
                                                  const float* __restrict__ be2,
                                                  const int* __restrict__ batch,
                                                  float* __restrict__ out) {
    __shared__ float lsum[NB * OUTC];   // 8 KB
    __shared__ float lmax[NB * OUTC];   // 8 KB
    __shared__ float lcnt[NB];
    int tid = threadIdx.x;
    for (int i = tid; i < NB * OUTC; i += 256) { lsum[i] = 0.f; lmax[i] = NEG_INF(); }
    if (tid < NB) lcnt[tid] = 0.f;
    int col = tid & 31;
    float mu  = d_stats2[col] * (1.0f / NN);
    float var = d_stats2[OUTC + col] * (1.0f / NN) - mu * mu;
    float m = rsqrtf(var + BN_EPS) * g2[col];
    float a = be2[col] - mu * m;
    int n0 = blockIdx.x * PB_NODES;
    __syncthreads();
    #pragma unroll 4
    for (int k = 0; k < PB_NODES * OUTC / 256; k++) {
        int idx = n0 * OUTC + k * 256 + tid;
        int node = idx >> 5;
        if (node < NN) {
            float v = fmaf(d_h2[idx], m, a);
            out[idx] = v;
            int b = batch[node];
            atomicAdd(&lsum[b * OUTC + col], v);
            atomicMaxF(&lmax[b * OUTC + col], v);
            if (col == 0) atomicAdd(&lcnt[b], 1.f);
        }
    }
    __syncthreads();
    int nlast = min(n0 + PB_NODES, NN) - 1;
    int bmin = batch[n0], bmax = batch[nlast];
    for (int j = tid; j < (bmax - bmin + 1) * OUTC; j += 256) {
        int b = bmin + (j >> 5), c = j & 31;
        float sv = lsum[b * OUTC + c];
        if (sv != 0.f) atomicAdd(&d_gsum[b * OUTC + c], sv);
        float mv = lmax[b * OUTC + c];
        if (mv > NEG_INF()) atomicMaxF(&d_gmax[b * OUTC + c], mv);
        if (c == 0) {
            float cv = lcnt[b];
            if (cv != 0.f) atomicAdd(&d_gcnt[b], cv);
        }
    }
}

// ---------------- final MLP ---------------------------------------------------
__global__ __launch_bounds__(256) void k_final(const float* __restrict__ fcW1,
                                               const float* __restrict__ fcb1,
                                               const float* __restrict__ fcW2,
                                               const float* __restrict__ fcb2,
                                               float* __restrict__ out) {
    __shared__ float g[NB * 2 * OUTC];
    __shared__ float t[NB * OUTC];
    int tid = threadIdx.x;
    for (int i = tid; i < NB * 2 * OUTC; i += 256) {
        int b = i >> 6, j = i & 63;
        float v;
        if (j < OUTC) {
            v = d_gsum[b * OUTC + j] / fmaxf(d_gcnt[b], 1.f);
        } else {
            v = d_gmax[b * OUTC + (j - OUTC)];
            if (v < -3e37f) v = 0.f;
        }
        g[i] = v;
    }
    __syncthreads();
    for (int i = tid; i < NB * OUTC; i += 256) {
        int b = i >> 5, o = i & 31;
        float acc = fcb1[o];
        #pragma unroll
        for (int j = 0; j < 2 * OUTC; j++) acc = fmaf(g[b * 64 + j], fcW1[j * OUTC + o], acc);
        t[i] = fmaxf(acc, 0.f);
    }
    __syncthreads();
    for (int i = tid; i < NB * OUTC; i += 256) {
        int b = i >> 5, o = i & 31;
        float acc = fcb2[o];
        #pragma unroll
        for (int j = 0; j < OUTC; j++) acc = fmaf(t[b * OUTC + j], fcW2[j * OUTC + o], acc);
        out[NN * OUTC + i] = acc;
    }
}

// =============================================================================
extern "C" void kernel_launch(void* const* d_in, const int* in_sizes, int n_in,
                              void* d_out, int out_size) {
    const float* x      = (const float*)d_in[0];
    const int*   ei     = (const int*)  d_in[1];
    const int*   batch  = (const int*)  d_in[2];
    const float* W1     = (const float*)d_in[3];
    const float* a_src1 = (const float*)d_in[4];
    const float* a_dst1 = (const float*)d_in[5];
    const float* g1     = (const float*)d_in[7];
    const float* be1    = (const float*)d_in[8];
    const float* W2     = (const float*)d_in[9];
    const float* a_src2 = (const float*)d_in[10];
    const float* a_dst2 = (const float*)d_in[11];
    const float* g2     = (const float*)d_in[13];
    const float* be2    = (const float*)d_in[14];
    const float* fcW1   = (const float*)d_in[15];
    const float* fcb1   = (const float*)d_in[16];
    const float* fcW2   = (const float*)d_in[17];
    const float* fcb2   = (const float*)d_in[18];
    float* out = (float*)d_out;

    // CSR build; gemm1 is launch #4 (lands in the ncu capture slot)
    k_deg_init<<<(NN + 255) / 256, 256>>>();
    k_deg_count<<<(EE / 4 + 255) / 256, 256>>>(ei);
    k_scan<<<1, 1024>>>();
    k_gemm1<<<(NN + 31) / 32, 256>>>(x, W1, a_src1, a_dst1);
    k_fill<<<(ET / 4 + 256) / 256, 256>>>(ei);

    // layer 1
    k_gat1<<<592, 256>>>();

    // layer 2
    k_gemm2<<<592, 256>>>(W2, g1, be1, a_src2, a_dst2);
    k_gat2<<<592, 256>>>();
    k_bn2_pool<<<(NN + PB_NODES - 1) / PB_NODES, 256>>>(g2, be2, batch, out);

    // graph head
    k_final<<<1, 256>>>(fcW1, fcb1, fcW2, fcb2, out);
}

// round 6
// speedup vs baseline: 2.0481x; 1.0404x over previous
#include <cuda_runtime.h>
#include <cuda_bf16.h>

#define NN   50000
#define EE   800000
#define ET   (EE + NN)
#define DIN  128
#define HIDN 64
#define OUTC 32
#define NB   64
#define NHEAD 4
#define C1   16

#define NEG_SLOPE 0.2f
#define BN_EPS 1e-5f

// ---------------- scratch ----------------------------------------------------
// xl1 PAIRED: [n][c] = float2( col c, col c+32 ), c in 0..31
__device__ float2 d_xl1p[NN * 32];
__device__ float d_es1[NN * NHEAD];
__device__ float d_ed1[NN * NHEAD];
__device__ float d_h1[NN * HIDN];
__device__ float d_stats1[2 * HIDN];

__device__ float d_xl2[NN * OUTC];
__device__ float d_es2[NN];
__device__ float d_ed2[NN];
__device__ float d_h2[NN * OUTC];
__device__ float d_stats2[2 * OUTC];

__device__ float d_gsum[NB * OUTC];
__device__ float d_gmax[NB * OUTC];
__device__ float d_gcnt[NB];

// CSR (by dst)
__device__ int d_deg[NN];
__device__ int d_off[NN + 1];
__device__ int d_cursor[NN];
__device__ int d_csrc[ET];

__device__ __forceinline__ float NEG_INF() { return __int_as_float(0xff800000); }

__device__ __forceinline__ void atomicMaxF(float* addr, float v) {
    if (v >= 0.0f) atomicMax((int*)addr, __float_as_int(v));
    else           atomicMin((unsigned int*)addr, __float_as_uint(v));
}

__device__ __forceinline__ float lrelu(float e) { return e > 0.f ? e : NEG_SLOPE * e; }

typedef unsigned long long ull;
__device__ __forceinline__ ull pack2dup(float x) {
    ull r;
    asm("mov.b64 %0, {%1,%2};" : "=l"(r) : "f"(x), "f"(x));
    return r;
}
__device__ __forceinline__ ull ffma2(ull a, ull b, ull c) {
    ull d;
    asm("fma.rn.f32x2 %0, %1, %2, %3;" : "=l"(d) : "l"(a), "l"(b), "l"(c));
    return d;
}
__device__ __forceinline__ float2 unpack2(ull v) {
    float2 f;
    asm("mov.b64 {%0,%1}, %2;" : "=f"(f.x), "=f"(f.y) : "l"(v));
    return f;
}

// ---------------- init + CSR build -------------------------------------------
__global__ __launch_bounds__(256) void k_deg_init() {
    int i = blockIdx.x * blockDim.x + threadIdx.x;
    if (i >= NN) return;
    d_deg[i] = 1;                       // self loop
    if (i < 2 * HIDN) d_stats1[i] = 0.f;
    if (i < 2 * OUTC) d_stats2[i] = 0.f;
    if (i < NB * OUTC) { d_gsum[i] = 0.f; d_gmax[i] = NEG_INF(); }
    if (i < NB) d_gcnt[i] = 0.f;
}

__global__ __launch_bounds__(256) void k_deg_count(const int* __restrict__ ei) {
    int i = blockIdx.x * blockDim.x + threadIdx.x;
    if (i >= EE / 4) return;
    int4 d4 = ((const int4*)(ei + EE))[i];
    atomicAdd(&d_deg[d4.x], 1);
    atomicAdd(&d_deg[d4.y], 1);
    atomicAdd(&d_deg[d4.z], 1);
    atomicAdd(&d_deg[d4.w], 1);
}

__global__ __launch_bounds__(1024) void k_scan() {
    __shared__ int part[1024];
    const int CH = (NN + 1023) / 1024;
    int t = threadIdx.x;
    int base = t * CH;
    int lim = min(base + CH, NN);
    int s = 0;
    for (int i = base; i < lim; i++) s += d_deg[i];
    part[t] = s;
    __syncthreads();
    for (int off = 1; off < 1024; off <<= 1) {
        int v = (t >= off) ? part[t - off] : 0;
        __syncthreads();
        part[t] += v;
        __syncthreads();
    }
    int run = (t == 0) ? 0 : part[t - 1];
    for (int i = base; i < lim; i++) {
        d_off[i] = run;
        d_cursor[i] = run;
        run += d_deg[i];
    }
    if (t == 0) d_off[NN] = part[1023];
}

__global__ __launch_bounds__(256) void k_fill(const int* __restrict__ ei) {
    int i = blockIdx.x * blockDim.x + threadIdx.x;
    if (i < EE / 4) {
        int4 s4 = ((const int4*)ei)[i];
        int4 t4 = ((const int4*)(ei + EE))[i];
        int p0 = atomicAdd(&d_cursor[t4.x], 1); d_csrc[p0] = s4.x;
        int p1 = atomicAdd(&d_cursor[t4.y], 1); d_csrc[p1] = s4.y;
        int p2 = atomicAdd(&d_cursor[t4.z], 1); d_csrc[p2] = s4.z;
        int p3 = atomicAdd(&d_cursor[t4.w], 1); d_csrc[p3] = s4.w;
    } else {
        int base = (i - EE / 4) * 4;
        #pragma unroll
        for (int r = 0; r < 4; r++) {
            int node = base + r;
            if (node < NN) {
                int pos = atomicAdd(&d_cursor[node], 1);
                d_csrc[pos] = node;
            }
        }
    }
}

// ---------------- GEMM1 + fused prep1 (transposed-x, paired rows) ------------
// 64 rows/block, K split in 2 halves of 64. Warp = 8 rows x 64 cols.
#define XPAD 68
__global__ __launch_bounds__(256) void k_gemm1(const float* __restrict__ x,
                                               const float* __restrict__ W1,
                                               const float* __restrict__ a_src,
                                               const float* __restrict__ a_dst) {
    __shared__ float Wsm[DIN * HIDN];                 // [k][col] 32 KB
    __shared__ __align__(16) float xs[64 * XPAD];     // [k_local][row] 17.4 KB
    __shared__ float sa_s[HIDN], sd_s[HIDN];
    int tid = threadIdx.x, lane = tid & 31, w = tid >> 5;
    for (int i = tid; i < DIN * HIDN; i += 256) Wsm[i] = W1[i];
    if (tid < HIDN) { sa_s[tid] = a_src[tid]; sd_s[tid] = a_dst[tid]; }

    int row0 = blockIdx.x * 64;
    int cp = lane;                    // col pair (cp, cp+32)
    int r0 = w * 8;                   // warp's 8 rows (local)
    ull acc[4][2] = {{0ull,0ull},{0ull,0ull},{0ull,0ull},{0ull,0ull}};

    #pragma unroll
    for (int half = 0; half < 2; half++) {
        // load x[rows, half*64 + 0..63] transposed into xs[k][row]
        for (int i = tid; i < 64 * 64; i += 256) {
            int rr = i >> 6, k = i & 63;
            int row = row0 + rr;
            xs[k * XPAD + rr] = (row < NN) ? x[row * DIN + half * 64 + k] : 0.f;
        }
        __syncthreads();
        int kw = half * 64;
        #pragma unroll 4
        for (int k = 0; k < 64; k++) {
            const float* xk = xs + k * XPAD + r0;
            ulonglong2 A = *(const ulonglong2*)xk;          // row pairs (0,1),(2,3)
            ulonglong2 B = *(const ulonglong2*)(xk + 4);    // row pairs (4,5),(6,7)
            ull w0d = pack2dup(Wsm[(kw + k) * HIDN + cp]);
            ull w1d = pack2dup(Wsm[(kw + k) * HIDN + cp + 32]);
            acc[0][0] = ffma2(A.x, w0d, acc[0][0]);
            acc[0][1] = ffma2(A.x, w1d, acc[0][1]);
            acc[1][0] = ffma2(A.y, w0d, acc[1][0]);
            acc[1][1] = ffma2(A.y, w1d, acc[1][1]);
            acc[2][0] = ffma2(B.x, w0d, acc[2][0]);
            acc[2][1] = ffma2(B.x, w1d, acc[2][1]);
            acc[3][0] = ffma2(B.y, w0d, acc[3][0]);
            acc[3][1] = ffma2(B.y, w1d, acc[3][1]);
        }
        __syncthreads();
    }

    // epilogue: per row, write paired xl1 + fused prep1
    float wa0 = sa_s[cp], wa1 = sa_s[cp + 32];
    float wd0 = sd_s[cp], wd1 = sd_s[cp + 32];
    int h0 = cp >> 4;
    #pragma unroll
    for (int rp = 0; rp < 4; rp++) {
        float2 o0 = unpack2(acc[rp][0]);   // col cp, rows (rA,rB)
        float2 o1 = unpack2(acc[rp][1]);   // col cp+32
        #pragma unroll
        for (int half = 0; half < 2; half++) {
            int row = row0 + r0 + 2 * rp + half;
            if (row >= NN) continue;       // uniform across warp
            float vx = half ? o0.y : o0.x;
            float vy = half ? o1.y : o1.x;
            d_xl1p[row * 32 + cp] = make_float2(vx, vy);
            float sax = vx * wa0, say = vy * wa1;
            float sdx = vx * wd0, sdy = vy * wd1;
            #pragma unroll
            for (int o = 8; o > 0; o >>= 1) {
                sax += __shfl_xor_sync(0xffffffffu, sax, o);
                say += __shfl_xor_sync(0xffffffffu, say, o);
                sdx += __shfl_xor_sync(0xffffffffu, sdx, o);
                sdy += __shfl_xor_sync(0xffffffffu, sdy, o);
            }
            if ((lane & 15) == 0) {
                d_es1[row * 4 + h0]     = sax;
                d_es1[row * 4 + h0 + 2] = say;
                d_ed1[row * 4 + h0]     = sdx;
                d_ed1[row * 4 + h0 + 2] = sdy;
            }
        }
    }
}

// ---------------- layer-1 GAT (smem-staged p) + fused BN1 stats --------------
__global__ __launch_bounds__(256) void k_gat1() {
    __shared__ float s_sum[HIDN], s_sq[HIDN];
    __shared__ float4 ps[8][32];   // {p0,p2,p1,p3}
    __shared__ int    se[8][32];
    int tid = threadIdx.x;
    int lane = tid & 31, w = tid >> 5;
    if (tid < HIDN) { s_sum[tid] = 0.f; s_sq[tid] = 0.f; }
    __syncthreads();
    int h0 = lane >> 4;
    const float2* pb = (const float2*)&ps[w][0];
    for (int n = blockIdx.x * 8 + w; n < NN; n += gridDim.x * 8) {
        int start = d_off[n], end = d_off[n + 1];
        float4 ed = *(const float4*)&d_ed1[n * 4];
        float acc0 = 0.f, acc1 = 0.f;
        float s0 = 0.f, s1 = 0.f, s2 = 0.f, s3 = 0.f;
        for (int j0 = start; j0 < end; j0 += 32) {
            int j = j0 + lane;
            int cnt = min(32, end - j0);
            int s = 0;
            float p0 = 0.f, p1 = 0.f, p2 = 0.f, p3 = 0.f;
            if (j < end) {
                s = d_csrc[j];
                float4 es = *(const float4*)&d_es1[s * 4];
                p0 = __expf(lrelu(es.x + ed.x));
                p1 = __expf(lrelu(es.y + ed.y));
                p2 = __expf(lrelu(es.z + ed.z));
                p3 = __expf(lrelu(es.w + ed.w));
            }
            s0 += p0; s1 += p1; s2 += p2; s3 += p3;
            ps[w][lane] = make_float4(p0, p2, p1, p3);
            se[w][lane] = s;
            __syncwarp();
            int t = 0;
            for (; t + 4 <= cnt; t += 4) {
                int ssb[4]; float2 pq[4]; float2 f[4];
                #pragma unroll
                for (int u = 0; u < 4; u++) {
                    ssb[u] = se[w][t + u];
                    pq[u]  = pb[2 * (t + u) + h0];
                }
                #pragma unroll
                for (int u = 0; u < 4; u++) f[u] = d_xl1p[ssb[u] * 32 + lane];
                #pragma unroll
                for (int u = 0; u < 4; u++) {
                    acc0 += pq[u].x * f[u].x;
                    acc1 += pq[u].y * f[u].y;
                }
            }
            for (; t < cnt; t++) {
                int ss = se[w][t];
                float2 pq = pb[2 * t + h0];
                float2 f = d_xl1p[ss * 32 + lane];
                acc0 += pq.x * f.x;
                acc1 += pq.y * f.y;
            }
            __syncwarp();
        }
        #pragma unroll
        for (int o = 16; o > 0; o >>= 1) {
            s0 += __shfl_xor_sync(0xffffffffu, s0, o);
            s1 += __shfl_xor_sync(0xffffffffu, s1, o);
            s2 += __shfl_xor_sync(0xffffffffu, s2, o);
            s3 += __shfl_xor_sync(0xffffffffu, s3, o);
        }
        float sA = h0 ? s1 : s0;
        float sB = h0 ? s3 : s2;
        float v0 = acc0 / (sA + 1e-16f);
        float v1 = acc1 / (sB + 1e-16f);
        d_h1[n * HIDN + lane]      = v0;
        d_h1[n * HIDN + 32 + lane] = v1;
        atomicAdd(&s_sum[lane], v0);       atomicAdd(&s_sum[32 + lane], v1);
        atomicAdd(&s_sq[lane], v0 * v0);   atomicAdd(&s_sq[32 + lane], v1 * v1);
    }
    __syncthreads();
    if (tid < HIDN) {
        atomicAdd(&d_stats1[tid], s_sum[tid]);
        atomicAdd(&d_stats1[HIDN + tid], s_sq[tid]);
    }
}

// ---------------- GEMM2 (BN1 apply fused) + fused prep2 ----------------------
__global__ __launch_bounds__(256) void k_gemm2(const float* __restrict__ W2,
                                               const float* __restrict__ g1,
                                               const float* __restrict__ be1,
                                               const float* __restrict__ a_src2,
                                               const float* __restrict__ a_dst2) {
    __shared__ float Ws[HIDN * OUTC];
    __shared__ float xs[8][HIDN];
    __shared__ float bnm[HIDN], bna[HIDN];
    int tid = threadIdx.x;
    for (int i = tid; i < HIDN * OUTC; i += 256) Ws[i] = W2[i];
    if (tid < HIDN) {
        float mu  = d_stats1[tid] * (1.0f / NN);
        float var = d_stats1[HIDN + tid] * (1.0f / NN) - mu * mu;
        float m = rsqrtf(var + BN_EPS) * g1[tid];
        bnm[tid] = m;
        bna[tid] = be1[tid] - mu * m;
    }
    int col = tid & 31;
    int r   = tid >> 5;
    float a2s = a_src2[col], a2d = a_dst2[col];
    for (int row0 = blockIdx.x * 8; row0 < NN; row0 += gridDim.x * 8) {
        __syncthreads();
        for (int i = tid; i < 8 * HIDN; i += 256) {
            int rr = i >> 6, k = i & 63;
            int row = row0 + rr;
            float hv = (row < NN) ? d_h1[row * HIDN + k] : 0.f;
            xs[rr][k] = fmaxf(fmaf(hv, bnm[k], bna[k]), 0.f);
        }
        __syncthreads();
        int row = row0 + r;
        if (row < NN) {
            float acc = 0.f;
            #pragma unroll
            for (int k = 0; k < HIDN; k++) acc = fmaf(xs[r][k], Ws[k * OUTC + col], acc);
            d_xl2[row * OUTC + col] = acc;
            float es = acc * a2s, edv = acc * a2d;
            #pragma unroll
            for (int o = 16; o > 0; o >>= 1) {
                es  += __shfl_xor_sync(0xffffffffu, es, o);
                edv += __shfl_xor_sync(0xffffffffu, edv, o);
            }
            if (col == 0) { d_es2[row] = es; d_ed2[row] = edv; }
        }
    }
}

// ---------------- layer-2 GAT + fused BN2 stats ------------------------------
__global__ __launch_bounds__(256) void k_gat2() {
    __shared__ float s_sum[OUTC], s_sq[OUTC];
    int tid = threadIdx.x;
    int lane = tid & 31, w = tid >> 5;
    if (tid < OUTC) { s_sum[tid] = 0.f; s_sq[tid] = 0.f; }
    __syncthreads();
    for (int n = blockIdx.x * 8 + w; n < NN; n += gridDim.x * 8) {
        int start = d_off[n], end = d_off[n + 1];
        float ed = d_ed2[n];
        float acc = 0.f, psum = 0.f;
        for (int j0 = start; j0 < end; j0 += 32) {
            int j = j0 + lane;
            int cnt = min(32, end - j0);
            int s = 0;
            float p = 0.f;
            if (j < end) {
                s = d_csrc[j];
                p = __expf(lrelu(d_es2[s] + ed));
            }
            psum += p;
            int t = 0;
            for (; t + 4 <= cnt; t += 4) {
                int ssb[4]; float pp[4], f[4];
                #pragma unroll
                for (int u = 0; u < 4; u++) {
                    ssb[u] = __shfl_sync(0xffffffffu, s, t + u);
                    pp[u]  = __shfl_sync(0xffffffffu, p, t + u);
                }
                #pragma unroll
                for (int u = 0; u < 4; u++) f[u] = d_xl2[ssb[u] * OUTC + lane];
                #pragma unroll
                for (int u = 0; u < 4; u++) acc += pp[u] * f[u];
            }
            for (; t < cnt; t++) {
                int   ss = __shfl_sync(0xffffffffu, s, t);
                float pp = __shfl_sync(0xffffffffu, p, t);
                acc += pp * d_xl2[ss * OUTC + lane];
            }
        }
        #pragma unroll
        for (int o = 16; o > 0; o >>= 1)
            psum += __shfl_xor_sync(0xffffffffu, psum, o);
        float v = acc / (psum + 1e-16f);
        d_h2[n * OUTC + lane] = v;
        atomicAdd(&s_sum[lane], v);
        atomicAdd(&s_sq[lane], v * v);
    }
    __syncthreads();
    if (tid < OUTC) {
        atomicAdd(&d_stats2[tid], s_sum[tid]);
        atomicAdd(&d_stats2[OUTC + tid], s_sq[tid]);
    }
}

// ---------------- BN2 + node_emb + pooling (smem-accumulated) ----------------
#define PB_NODES 256
__global__ __launch_bounds__(256) void k_bn2_pool(const float* __restrict__ g2,
                                                  const float* __restrict__ be2,
                                                  const int* __restrict__ batch,
                                                  float* __restrict__ out) {
    __shared__ float lsum[NB * OUTC];
    __shared__ float lmax[NB * OUTC];
    __shared__ float lcnt[NB];
    int tid = threadIdx.x;
    for (int i = tid; i < NB * OUTC; i += 256) { lsum[i] = 0.f; lmax[i] = NEG_INF(); }
    if (tid < NB) lcnt[tid] = 0.f;
    int col = tid & 31;
    float mu  = d_stats2[col] * (1.0f / NN);
    float var = d_stats2[OUTC + col] * (1.0f / NN) - mu * mu;
    float m = rsqrtf(var + BN_EPS) * g2[col];
    float a = be2[col] - mu * m;
    int n0 = blockIdx.x * PB_NODES;
    __syncthreads();
    #pragma unroll 4
    for (int k = 0; k < PB_NODES * OUTC / 256; k++) {
        int idx = n0 * OUTC + k * 256 + tid;
        int node = idx >> 5;
        if (node < NN) {
            float v = fmaf(d_h2[idx], m, a);
            out[idx] = v;
            int b = batch[node];
            atomicAdd(&lsum[b * OUTC + col], v);
            atomicMaxF(&lmax[b * OUTC + col], v);
            if (col == 0) atomicAdd(&lcnt[b], 1.f);
        }
    }
    __syncthreads();
    int nlast = min(n0 + PB_NODES, NN) - 1;
    int bmin = batch[n0], bmax = batch[nlast];
    for (int j = tid; j < (bmax - bmin + 1) * OUTC; j += 256) {
        int b = bmin + (j >> 5), c = j & 31;
        float sv = lsum[b * OUTC + c];
        if (sv != 0.f) atomicAdd(&d_gsum[b * OUTC + c], sv);
        float mv = lmax[b * OUTC + c];
        if (mv > NEG_INF()) atomicMaxF(&d_gmax[b * OUTC + c], mv);
        if (c == 0) {
            float cv = lcnt[b];
            if (cv != 0.f) atomicAdd(&d_gcnt[b], cv);
        }
    }
}

// ---------------- final MLP ---------------------------------------------------
__global__ __launch_bounds__(256) void k_final(const float* __restrict__ fcW1,
                                               const float* __restrict__ fcb1,
                                               const float* __restrict__ fcW2,
                                               const float* __restrict__ fcb2,
                                               float* __restrict__ out) {
    __shared__ float g[NB * 2 * OUTC];
    __shared__ float t[NB * OUTC];
    int tid = threadIdx.x;
    for (int i = tid; i < NB * 2 * OUTC; i += 256) {
        int b = i >> 6, j = i & 63;
        float v;
        if (j < OUTC) {
            v = d_gsum[b * OUTC + j] / fmaxf(d_gcnt[b], 1.f);
        } else {
            v = d_gmax[b * OUTC + (j - OUTC)];
            if (v < -3e37f) v = 0.f;
        }
        g[i] = v;
    }
    __syncthreads();
    for (int i = tid; i < NB * OUTC; i += 256) {
        int b = i >> 5, o = i & 31;
        float acc = fcb1[o];
        #pragma unroll
        for (int j = 0; j < 2 * OUTC; j++) acc = fmaf(g[b * 64 + j], fcW1[j * OUTC + o], acc);
        t[i] = fmaxf(acc, 0.f);
    }
    __syncthreads();
    for (int i = tid; i < NB * OUTC; i += 256) {
        int b = i >> 5, o = i & 31;
        float acc = fcb2[o];
        #pragma unroll
        for (int j = 0; j < OUTC; j++) acc = fmaf(t[b * OUTC + j], fcW2[j * OUTC + o], acc);
        out[NN * OUTC + i] = acc;
    }
}

// =============================================================================
extern "C" void kernel_launch(void* const* d_in, const int* in_sizes, int n_in,
                              void* d_out, int out_size) {
    const float* x      = (const float*)d_in[0];
    const int*   ei     = (const int*)  d_in[1];
    const int*   batch  = (const int*)  d_in[2];
    const float* W1     = (const float*)d_in[3];
    const float* a_src1 = (const float*)d_in[4];
    const float* a_dst1 = (const float*)d_in[5];
    const float* g1     = (const float*)d_in[7];
    const float* be1    = (const float*)d_in[8];
    const float* W2     = (const float*)d_in[9];
    const float* a_src2 = (const float*)d_in[10];
    const float* a_dst2 = (const float*)d_in[11];
    const float* g2     = (const float*)d_in[13];
    const float* be2    = (const float*)d_in[14];
    const float* fcW1   = (const float*)d_in[15];
    const float* fcb1   = (const float*)d_in[16];
    const float* fcW2   = (const float*)d_in[17];
    const float* fcb2   = (const float*)d_in[18];
    float* out = (float*)d_out;

    // launches 1-3, then gemm1 = launch #4 (ncu capture slot)
    k_deg_init<<<(NN + 255) / 256, 256>>>();
    k_deg_count<<<(EE / 4 + 255) / 256, 256>>>(ei);
    k_scan<<<1, 1024>>>();
    k_gemm1<<<(NN + 63) / 64, 256>>>(x, W1, a_src1, a_dst1);
    k_fill<<<((EE / 4 + (NN + 3) / 4) + 255) / 256, 256>>>(ei);

    k_gat1<<<592, 256>>>();

    k_gemm2<<<592, 256>>>(W2, g1, be1, a_src2, a_dst2);
    k_gat2<<<592, 256>>>();
    k_bn2_pool<<<(NN + PB_NODES - 1) / PB_NODES, 256>>>(g2, be2, batch, out);

    k_final<<<1, 256>>>(fcW1, fcb1, fcW2, fcb2, out);
}

// round 9
// speedup vs baseline: 2.8920x; 1.4120x over previous
#include <cuda_runtime.h>
#include <cuda_bf16.h>

#define NN   50000
#define EE   800000
#define ET   (EE + NN)
#define DIN  128
#define HIDN 64
#define OUTC 32
#define NB   64
#define NHEAD 4

#define NEG_SLOPE 0.2f
#define BN_EPS 1e-5f

// ---------------- scratch (zero-initialized at module load; k_final restores) -
__device__ float2 d_xl1p[NN * 32];     // paired: [n][c] = (col c, col c+32)
__device__ float d_es1[NN * NHEAD];
__device__ float d_ed1[NN * NHEAD];
__device__ float d_h1[NN * HIDN];
__device__ float d_stats1[2 * HIDN];   // reset by k_final

__device__ float d_xl2[NN * OUTC];
__device__ float d_es2[NN];
__device__ float d_ed2[NN];
__device__ float d_h2[NN * OUTC];
__device__ float d_stats2[2 * OUTC];   // reset by k_final

__device__ float d_gsum[NB * OUTC];    // reset by k_final
__device__ float d_gmax[NB * OUTC];    // reset by k_final (to -inf)
__device__ float d_gcnt[NB];           // reset by k_final

// CSR (by dst)
__device__ int d_deg[NN];              // reset by k_alloc
__device__ int d_off[NN];
__device__ int d_end[NN];
__device__ int d_cursor[NN];
__device__ int d_csrc[ET];
__device__ int d_total;                // reset by k_final

__device__ __forceinline__ float NEG_INF() { return __int_as_float(0xff800000); }

__device__ __forceinline__ void atomicMaxF(float* addr, float v) {
    if (v >= 0.0f) atomicMax((int*)addr, __float_as_int(v));
    else           atomicMin((unsigned int*)addr, __float_as_uint(v));
}

__device__ __forceinline__ float lrelu(float e) { return e > 0.f ? e : NEG_SLOPE * e; }

typedef unsigned long long ull;
__device__ __forceinline__ ull pack2dup(float x) {
    ull r;
    asm("mov.b64 %0, {%1,%2};" : "=l"(r) : "f"(x), "f"(x));
    return r;
}
__device__ __forceinline__ ull ffma2(ull a, ull b, ull c) {
    ull d;
    asm("fma.rn.f32x2 %0, %1, %2, %3;" : "=l"(d) : "l"(a), "l"(b), "l"(c));
    return d;
}
__device__ __forceinline__ float2 unpack2(ull v) {
    float2 f;
    asm("mov.b64 {%0,%1}, %2;" : "=f"(f.x), "=f"(f.y) : "l"(v));
    return f;
}

// ---------------- CSR build ---------------------------------------------------
__global__ __launch_bounds__(256) void k_deg_count(const int* __restrict__ ei) {
    int i = blockIdx.x * blockDim.x + threadIdx.x;
    if (i >= EE / 4) return;
    int4 d4 = ((const int4*)(ei + EE))[i];
    atomicAdd(&d_deg[d4.x], 1);
    atomicAdd(&d_deg[d4.y], 1);
    atomicAdd(&d_deg[d4.z], 1);
    atomicAdd(&d_deg[d4.w], 1);
}

// Parallel segment allocation: per-block scan + one atomicAdd for base.
// Segments are NOT in node order (irrelevant: accessed via off/end only).
__global__ __launch_bounds__(256) void k_alloc() {
    __shared__ int wsum[8];
    __shared__ int sbase;
    int tid = threadIdx.x, lane = tid & 31, w = tid >> 5;
    int i = blockIdx.x * 256 + tid;
    int cnt = (i < NN) ? d_deg[i] + 1 : 0;      // +1 self loop
    int sc = cnt;
    #pragma unroll
    for (int o = 1; o < 32; o <<= 1) {
        int v = __shfl_up_sync(0xffffffffu, sc, o);
        if (lane >= o) sc += v;
    }
    if (lane == 31) wsum[w] = sc;
    __syncthreads();
    if (w == 0) {
        int s = (lane < 8) ? wsum[lane] : 0;
        #pragma unroll
        for (int o = 1; o < 8; o <<= 1) {
            int v = __shfl_up_sync(0xffffffffu, s, o);
            if (lane >= o) s += v;
        }
        if (lane < 8) wsum[lane] = s;
        if (lane == 7) sbase = atomicAdd(&d_total, s);
    }
    __syncthreads();
    if (i < NN) {
        int base = sbase + (w > 0 ? wsum[w - 1] : 0) + sc - cnt;
        d_off[i] = base;
        d_cursor[i] = base;
        d_end[i] = base + cnt;
        d_deg[i] = 0;                            // restore for next replay
    }
}

__global__ __launch_bounds__(256) void k_fill(const int* __restrict__ ei) {
    int i = blockIdx.x * blockDim.x + threadIdx.x;
    if (i < EE / 4) {
        int4 s4 = ((const int4*)ei)[i];
        int4 t4 = ((const int4*)(ei + EE))[i];
        int p0 = atomicAdd(&d_cursor[t4.x], 1); d_csrc[p0] = s4.x;
        int p1 = atomicAdd(&d_cursor[t4.y], 1); d_csrc[p1] = s4.y;
        int p2 = atomicAdd(&d_cursor[t4.z], 1); d_csrc[p2] = s4.z;
        int p3 = atomicAdd(&d_cursor[t4.w], 1); d_csrc[p3] = s4.w;
    } else {
        int base = (i - EE / 4) * 4;
        #pragma unroll
        for (int r = 0; r < 4; r++) {
            int node = base + r;
            if (node < NN) {
                int pos = atomicAdd(&d_cursor[node], 1);
                d_csrc[pos] = node;
            }
        }
    }
}

// ---------------- GEMM1 + fused prep1 (persistent, W loaded once) ------------
#define XPAD 68
#define NTILE1 ((NN + 63) / 64)
__global__ __launch_bounds__(256) void k_gemm1(const float* __restrict__ x,
                                               const float* __restrict__ W1,
                                               const float* __restrict__ a_src,
                                               const float* __restrict__ a_dst) {
    __shared__ float Wsm[DIN * HIDN];                 // 32 KB
    __shared__ __align__(16) float xs[64 * XPAD];     // 17.4 KB
    __shared__ float sa_s[HIDN], sd_s[HIDN];
    int tid = threadIdx.x, lane = tid & 31, w = tid >> 5;
    for (int i = tid; i < DIN * HIDN; i += 256) Wsm[i] = W1[i];
    if (tid < HIDN) { sa_s[tid] = a_src[tid]; sd_s[tid] = a_dst[tid]; }
    __syncthreads();
    int cp = lane;
    int r0 = w * 8;
    float wa0 = sa_s[cp], wa1 = sa_s[cp + 32];
    float wd0 = sd_s[cp], wd1 = sd_s[cp + 32];
    int h0 = cp >> 4;

    for (int tile = blockIdx.x; tile < NTILE1; tile += gridDim.x) {
        int row0 = tile * 64;
        ull acc[4][2] = {{0ull,0ull},{0ull,0ull},{0ull,0ull},{0ull,0ull}};
        #pragma unroll
        for (int half = 0; half < 2; half++) {
            __syncthreads();
            for (int i = tid; i < 64 * 64; i += 256) {
                int rr = i >> 6, k = i & 63;
                int row = row0 + rr;
                xs[k * XPAD + rr] = (row < NN) ? x[row * DIN + half * 64 + k] : 0.f;
            }
            __syncthreads();
            int kw = half * 64;
            #pragma unroll 4
            for (int k = 0; k < 64; k++) {
                const float* xk = xs + k * XPAD + r0;
                ulonglong2 A = *(const ulonglong2*)xk;
                ulonglong2 B = *(const ulonglong2*)(xk + 4);
                ull w0d = pack2dup(Wsm[(kw + k) * HIDN + cp]);
                ull w1d = pack2dup(Wsm[(kw + k) * HIDN + cp + 32]);
                acc[0][0] = ffma2(A.x, w0d, acc[0][0]);
                acc[0][1] = ffma2(A.x, w1d, acc[0][1]);
                acc[1][0] = ffma2(A.y, w0d, acc[1][0]);
                acc[1][1] = ffma2(A.y, w1d, acc[1][1]);
                acc[2][0] = ffma2(B.x, w0d, acc[2][0]);
                acc[2][1] = ffma2(B.x, w1d, acc[2][1]);
                acc[3][0] = ffma2(B.y, w0d, acc[3][0]);
                acc[3][1] = ffma2(B.y, w1d, acc[3][1]);
            }
        }
        #pragma unroll
        for (int rp = 0; rp < 4; rp++) {
            float2 o0 = unpack2(acc[rp][0]);
            float2 o1 = unpack2(acc[rp][1]);
            #pragma unroll
            for (int half = 0; half < 2; half++) {
                int row = row0 + r0 + 2 * rp + half;
                if (row >= NN) continue;
                float vx = half ? o0.y : o0.x;
                float vy = half ? o1.y : o1.x;
                d_xl1p[row * 32 + cp] = make_float2(vx, vy);
                float sax = vx * wa0, say = vy * wa1;
                float sdx = vx * wd0, sdy = vy * wd1;
                #pragma unroll
                for (int o = 8; o > 0; o >>= 1) {
                    sax += __shfl_xor_sync(0xffffffffu, sax, o);
                    say += __shfl_xor_sync(0xffffffffu, say, o);
                    sdx += __shfl_xor_sync(0xffffffffu, sdx, o);
                    sdy += __shfl_xor_sync(0xffffffffu, sdy, o);
                }
                if ((lane & 15) == 0) {
                    d_es1[row * 4 + h0]     = sax;
                    d_es1[row * 4 + h0 + 2] = say;
                    d_ed1[row * 4 + h0]     = sdx;
                    d_ed1[row * 4 + h0 + 2] = sdy;
                }
            }
        }
    }
}

// ---------------- layer-1 GAT + fused BN1 stats ------------------------------
__global__ __launch_bounds__(256) void k_gat1() {
    __shared__ float s_sum[HIDN], s_sq[HIDN];
    __shared__ float4 ps[8][32];   // {p0,p2,p1,p3}
    __shared__ int    se[8][32];
    int tid = threadIdx.x;
    int lane = tid & 31, w = tid >> 5;
    if (tid < HIDN) { s_sum[tid] = 0.f; s_sq[tid] = 0.f; }
    __syncthreads();
    int h0 = lane >> 4;
    const float2* pb = (const float2*)&ps[w][0];
    for (int n = blockIdx.x * 8 + w; n < NN; n += gridDim.x * 8) {
        int start = d_off[n], end = d_end[n];
        float4 ed = *(const float4*)&d_ed1[n * 4];
        float acc0 = 0.f, acc1 = 0.f;
        float s0 = 0.f, s1 = 0.f, s2 = 0.f, s3 = 0.f;
        for (int j0 = start; j0 < end; j0 += 32) {
            int j = j0 + lane;
            int cnt = min(32, end - j0);
            int s = 0;
            float p0 = 0.f, p1 = 0.f, p2 = 0.f, p3 = 0.f;
            if (j < end) {
                s = d_csrc[j];
                float4 es = *(const float4*)&d_es1[s * 4];
                p0 = __expf(lrelu(es.x + ed.x));
                p1 = __expf(lrelu(es.y + ed.y));
                p2 = __expf(lrelu(es.z + ed.z));
                p3 = __expf(lrelu(es.w + ed.w));
            }
            s0 += p0; s1 += p1; s2 += p2; s3 += p3;
            ps[w][lane] = make_float4(p0, p2, p1, p3);
            se[w][lane] = s;
            __syncwarp();
            int t = 0;
            for (; t + 4 <= cnt; t += 4) {
                int ssb[4]; float2 pq[4]; float2 f[4];
                #pragma unroll
                for (int u = 0; u < 4; u++) {
                    ssb[u] = se[w][t + u];
                    pq[u]  = pb[2 * (t + u) + h0];
                }
                #pragma unroll
                for (int u = 0; u < 4; u++) f[u] = d_xl1p[ssb[u] * 32 + lane];
                #pragma unroll
                for (int u = 0; u < 4; u++) {
                    acc0 += pq[u].x * f[u].x;
                    acc1 += pq[u].y * f[u].y;
                }
            }
            for (; t < cnt; t++) {
                int ss = se[w][t];
                float2 pq = pb[2 * t + h0];
                float2 f = d_xl1p[ss * 32 + lane];
                acc0 += pq.x * f.x;
                acc1 += pq.y * f.y;
            }
            __syncwarp();
        }
        #pragma unroll
        for (int o = 16; o > 0; o >>= 1) {
            s0 += __shfl_xor_sync(0xffffffffu, s0, o);
            s1 += __shfl_xor_sync(0xffffffffu, s1, o);
            s2 += __shfl_xor_sync(0xffffffffu, s2, o);
            s3 += __shfl_xor_sync(0xffffffffu, s3, o);
        }
        float sA = h0 ? s1 : s0;
        float sB = h0 ? s3 : s2;
        float v0 = acc0 / (sA + 1e-16f);
        float v1 = acc1 / (sB + 1e-16f);
        d_h1[n * HIDN + lane]      = v0;
        d_h1[n * HIDN + 32 + lane] = v1;
        atomicAdd(&s_sum[lane], v0);       atomicAdd(&s_sum[32 + lane], v1);
        atomicAdd(&s_sq[lane], v0 * v0);   atomicAdd(&s_sq[32 + lane], v1 * v1);
    }
    __syncthreads();
    if (tid < HIDN) {
        atomicAdd(&d_stats1[tid], s_sum[tid]);
        atomicAdd(&d_stats1[HIDN + tid], s_sq[tid]);
    }
}

// ---------------- GEMM2 (BN1 fused) + fused prep2, 16-row tiles --------------
__global__ __launch_bounds__(256) void k_gemm2(const float* __restrict__ W2,
                                               const float* __restrict__ g1,
                                               const float* __restrict__ be1,
                                               const float* __restrict__ a_src2,
                                               const float* __restrict__ a_dst2) {
    __shared__ float Ws[HIDN * OUTC];
    __shared__ float xs[16][HIDN];
    __shared__ float bnm[HIDN], bna[HIDN];
    int tid = threadIdx.x;
    for (int i = tid; i < HIDN * OUTC; i += 256) Ws[i] = W2[i];
    if (tid < HIDN) {
        float mu  = d_stats1[tid] * (1.0f / NN);
        float var = d_stats1[HIDN + tid] * (1.0f / NN) - mu * mu;
        float m = rsqrtf(var + BN_EPS) * g1[tid];
        bnm[tid] = m;
        bna[tid] = be1[tid] - mu * m;
    }
    int col = tid & 31;
    int r   = tid >> 5;
    float a2s = a_src2[col], a2d = a_dst2[col];
    for (int row0 = blockIdx.x * 16; row0 < NN; row0 += gridDim.x * 16) {
        __syncthreads();
        for (int i = tid; i < 16 * HIDN; i += 256) {
            int rr = i >> 6, k = i & 63;
            int row = row0 + rr;
            float hv = (row < NN) ? d_h1[row * HIDN + k] : 0.f;
            xs[rr][k] = fmaxf(fmaf(hv, bnm[k], bna[k]), 0.f);
        }
        __syncthreads();
        #pragma unroll
        for (int half = 0; half < 2; half++) {
            int rr = r + half * 8;
            int row = row0 + rr;
            if (row < NN) {
                float acc = 0.f;
                #pragma unroll
                for (int k = 0; k < HIDN; k++) acc = fmaf(xs[rr][k], Ws[k * OUTC + col], acc);
                d_xl2[row * OUTC + col] = acc;
                float es = acc * a2s, edv = acc * a2d;
                #pragma unroll
                for (int o = 16; o > 0; o >>= 1) {
                    es  += __shfl_xor_sync(0xffffffffu, es, o);
                    edv += __shfl_xor_sync(0xffffffffu, edv, o);
                }
                if (col == 0) { d_es2[row] = es; d_ed2[row] = edv; }
            }
        }
    }
}

// ---------------- layer-2 GAT + fused BN2 stats ------------------------------
__global__ __launch_bounds__(256) void k_gat2() {
    __shared__ float s_sum[OUTC], s_sq[OUTC];
    int tid = threadIdx.x;
    int lane = tid & 31, w = tid >> 5;
    if (tid < OUTC) { s_sum[tid] = 0.f; s_sq[tid] = 0.f; }
    __syncthreads();
    for (int n = blockIdx.x * 8 + w; n < NN; n += gridDim.x * 8) {
        int start = d_off[n], end = d_end[n];
        float ed = d_ed2[n];
        float acc = 0.f, psum = 0.f;
        for (int j0 = start; j0 < end; j0 += 32) {
            int j = j0 + lane;
            int cnt = min(32, end - j0);
            int s = 0;
            float p = 0.f;
            if (j < end) {
                s = d_csrc[j];
                p = __expf(lrelu(d_es2[s] + ed));
            }
            psum += p;
            int t = 0;
            for (; t + 4 <= cnt; t += 4) {
                int ssb[4]; float pp[4], f[4];
                #pragma unroll
                for (int u = 0; u < 4; u++) {
                    ssb[u] = __shfl_sync(0xffffffffu, s, t + u);
                    pp[u]  = __shfl_sync(0xffffffffu, p, t + u);
                }
                #pragma unroll
                for (int u = 0; u < 4; u++) f[u] = d_xl2[ssb[u] * OUTC + lane];
                #pragma unroll
                for (int u = 0; u < 4; u++) acc += pp[u] * f[u];
            }
            for (; t < cnt; t++) {
                int   ss = __shfl_sync(0xffffffffu, s, t);
                float pp = __shfl_sync(0xffffffffu, p, t);
                acc += pp * d_xl2[ss * OUTC + lane];
            }
        }
        #pragma unroll
        for (int o = 16; o > 0; o >>= 1)
            psum += __shfl_xor_sync(0xffffffffu, psum, o);
        float v = acc / (psum + 1e-16f);
        d_h2[n * OUTC + lane] = v;
        atomicAdd(&s_sum[lane], v);
        atomicAdd(&s_sq[lane], v * v);
    }
    __syncthreads();
    if (tid < OUTC) {
        atomicAdd(&d_stats2[tid], s_sum[tid]);
        atomicAdd(&d_stats2[OUTC + tid], s_sq[tid]);
    }
}

// ---------------- BN2 + node_emb + pooling (smem-accumulated) ----------------
#define PB_NODES 256
__global__ __launch_bounds__(256) void k_bn2_pool(const float* __restrict__ g2,
                                                  const float* __restrict__ be2,
                                                  const int* __restrict__ batch,
                                                  float* __restrict__ out) {
    __shared__ float lsum[NB * OUTC];
    __shared__ float lmax[NB * OUTC];
    __shared__ float lcnt[NB];
    int tid = threadIdx.x;
    for (int i = tid; i < NB * OUTC; i += 256) { lsum[i] = 0.f; lmax[i] = NEG_INF(); }
    if (tid < NB) lcnt[tid] = 0.f;
    int col = tid & 31;
    float mu  = d_stats2[col] * (1.0f / NN);
    float var = d_stats2[OUTC + col] * (1.0f / NN) - mu * mu;
    float m = rsqrtf(var + BN_EPS) * g2[col];
    float a = be2[col] - mu * m;
    int n0 = blockIdx.x * PB_NODES;
    __syncthreads();
    #pragma unroll 4
    for (int k = 0; k < PB_NODES * OUTC / 256; k++) {
        int idx = n0 * OUTC + k * 256 + tid;
        int node = idx >> 5;
        if (node < NN) {
            float v = fmaf(d_h2[idx], m, a);
            out[idx] = v;
            int b = batch[node];
            atomicAdd(&lsum[b * OUTC + col], v);
            atomicMaxF(&lmax[b * OUTC + col], v);
            if (col == 0) atomicAdd(&lcnt[b], 1.f);
        }
    }
    __syncthreads();
    int nlast = min(n0 + PB_NODES, NN) - 1;
    int bmin = batch[n0], bmax = batch[nlast];
    for (int j = tid; j < (bmax - bmin + 1) * OUTC; j += 256) {
        int b = bmin + (j >> 5), c = j & 31;
        float sv = lsum[b * OUTC + c];
        if (sv != 0.f) atomicAdd(&d_gsum[b * OUTC + c], sv);
        float mv = lmax[b * OUTC + c];
        if (mv > NEG_INF()) atomicMaxF(&d_gmax[b * OUTC + c], mv);
        if (c == 0) {
            float cv = lcnt[b];
            if (cv != 0.f) atomicAdd(&d_gcnt[b], cv);
        }
    }
}

// ---------------- final MLP + scratch restore --------------------------------
__global__ __launch_bounds__(256) void k_final(const float* __restrict__ fcW1,
                                               const float* __restrict__ fcb1,
                                               const float* __restrict__ fcW2,
                                               const float* __restrict__ fcb2,
                                               float* __restrict__ out) {
    __shared__ float g[NB * 2 * OUTC];
    __shared__ float t[NB * OUTC];
    int tid = threadIdx.x;
    for (int i = tid; i < NB * 2 * OUTC; i += 256) {
        int b = i >> 6, j = i & 63;
        float v;
        if (j < OUTC) {
            v = d_gsum[b * OUTC + j] / fmaxf(d_gcnt[b], 1.f);
        } else {
            v = d_gmax[b * OUTC + (j - OUTC)];
            if (v < -3e37f) v = 0.f;
        }
        g[i] = v;
    }
    __syncthreads();
    // restore accumulators for the next replay
    for (int i = tid; i < NB * OUTC; i += 256) { d_gsum[i] = 0.f; d_gmax[i] = NEG_INF(); }
    if (tid < NB) d_gcnt[tid] = 0.f;
    if (tid < 2 * HIDN) d_stats1[tid] = 0.f;
    if (tid < 2 * OUTC) d_stats2[tid] = 0.f;
    if (tid == 0) d_total = 0;
    // MLP
    for (int i = tid; i < NB * OUTC; i += 256) {
        int b = i >> 5, o = i & 31;
        float acc = fcb1[o];
        #pragma unroll
        for (int j = 0; j < 2 * OUTC; j++) acc = fmaf(g[b * 64 + j], fcW1[j * OUTC + o], acc);
        t[i] = fmaxf(acc, 0.f);
    }
    __syncthreads();
    for (int i = tid; i < NB * OUTC; i += 256) {
        int b = i >> 5, o = i & 31;
        float acc = fcb2[o];
        #pragma unroll
        for (int j = 0; j < OUTC; j++) acc = fmaf(t[b * OUTC + j], fcW2[j * OUTC + o], acc);
        out[NN * OUTC + i] = acc;
    }
}

// =============================================================================
extern "C" void kernel_launch(void* const* d_in, const int* in_sizes, int n_in,
                              void* d_out, int out_size) {
    const float* x      = (const float*)d_in[0];
    const int*   ei     = (const int*)  d_in[1];
    const int*   batch  = (const int*)  d_in[2];
    const float* W1     = (const float*)d_in[3];
    const float* a_src1 = (const float*)d_in[4];
    const float* a_dst1 = (const float*)d_in[5];
    const float* g1     = (const float*)d_in[7];
    const float* be1    = (const float*)d_in[8];
    const float* W2     = (const float*)d_in[9];
    const float* a_src2 = (const float*)d_in[10];
    const float* a_dst2 = (const float*)d_in[11];
    const float* g2     = (const float*)d_in[13];
    const float* be2    = (const float*)d_in[14];
    const float* fcW1   = (const float*)d_in[15];
    const float* fcb1   = (const float*)d_in[16];
    const float* fcW2   = (const float*)d_in[17];
    const float* fcb2   = (const float*)d_in[18];
    float* out = (float*)d_out;

    k_deg_count<<<(EE / 4 + 255) / 256, 256>>>(ei);
    k_alloc<<<(NN + 255) / 256, 256>>>();
    k_fill<<<((EE / 4 + (NN + 3) / 4) + 255) / 256, 256>>>(ei);
    k_gemm1<<<592, 256>>>(x, W1, a_src1, a_dst1);   // launch #4: ncu capture slot

    k_gat1<<<592, 256>>>();

    k_gemm2<<<592, 256>>>(W2, g1, be1, a_src2, a_dst2);
    k_gat2<<<592, 256>>>();
    k_bn2_pool<<<(NN + PB_NODES - 1) / PB_NODES, 256>>>(g2, be2, batch, out);

    k_final<<<1, 256>>>(fcW1, fcb1, fcW2, fcb2, out);
}